// round 12
// baseline (speedup 1.0000x reference)
#include <cuda_runtime.h>
#include <cuda_bf16.h>
#include <math.h>
#include <stdint.h>

#define HID 128
#define NL 4
#define TPI 258
#define NTILE_TOT (TPI*4)
#define GRID 152
#define THREADS 256
#define PART 16908288              // 1032*128*128 elements per component

__device__ unsigned short g_act0[4*(size_t)PART];
__device__ unsigned short g_act1[4*(size_t)PART];
__device__ unsigned short g_wimg[NL * 65536];
__device__ float g_sx[256];

__device__ __forceinline__ uint32_t smem_u32(const void* p) {
    uint32_t a;
    asm("{ .reg .u64 t; cvta.to.shared.u64 t, %1; cvt.u32.u64 %0, t; }" : "=r"(a) : "l"(p));
    return a;
}
__device__ __forceinline__ void ldsm4(uint32_t& r0, uint32_t& r1, uint32_t& r2, uint32_t& r3, uint32_t addr) {
    asm volatile("ldmatrix.sync.aligned.m8n8.x4.shared.b16 {%0,%1,%2,%3}, [%4];"
        : "=r"(r0), "=r"(r1), "=r"(r2), "=r"(r3) : "r"(addr));
}
__device__ __forceinline__ void mma16816(float* d, const uint32_t* a, uint32_t b0, uint32_t b1) {
    asm volatile("mma.sync.aligned.m16n8k16.row.col.f32.bf16.bf16.f32 "
        "{%0,%1,%2,%3}, {%4,%5,%6,%7}, {%8,%9}, {%0,%1,%2,%3};"
        : "+f"(d[0]), "+f"(d[1]), "+f"(d[2]), "+f"(d[3])
        : "r"(a[0]), "r"(a[1]), "r"(a[2]), "r"(a[3]), "r"(b0), "r"(b1));
}
#define CP16(dst, src) asm volatile("cp.async.cg.shared.global [%0], [%1], 16;" :: "r"(dst), "l"(src))
#define CP_COMMIT()    asm volatile("cp.async.commit_group;" ::: "memory")
#define CP_WAIT1()     asm volatile("cp.async.wait_group 1;" ::: "memory")

__device__ __forceinline__ float gelu_exact(float v) {
    return 0.5f * v * (1.0f + erff(v * 0.70710678118654752f));
}
__device__ __forceinline__ uint32_t pack_hi2(float a, float b) {
    return __byte_perm(__float_as_uint(a), __float_as_uint(b), 0x7632);
}
__device__ __forceinline__ uint32_t pack_lo2(float a, float b) {
    float ra = a - __uint_as_float(__float_as_uint(a) & 0xffff0000u);
    float rb = b - __uint_as_float(__float_as_uint(b) & 0xffff0000u);
    __nv_bfloat162 p = __floats2bfloat162_rn(ra, rb);
    return *reinterpret_cast<uint32_t*>(&p);
}
__device__ __forceinline__ void decode_ctile(int tt, int& r, int& x0) {
    if (tt < 254)      { r = 1 + (tt >> 1); x0 = (tt & 1) << 7; }
    else if (tt < 256) { r = 0;             x0 = (tt - 254) << 7; }
    else               { r = 128;           x0 = (tt - 256) << 7; }
}

// one k64 chunk of one GEMM bank: warp tile 32m x 64n, 3-combo bf16 split
__device__ __forceinline__ void mma_chunk(
    float (&acc)[2][8][4], uint32_t aHi, uint32_t bHi,
    const uint32_t (&arow)[2], const uint32_t (&brow)[4],
    uint32_t a_c16, uint32_t b_c16, uint32_t xm)
{
    uint32_t aLo = aHi + 16384u;
    uint32_t bLo = bHi + 32768u;
    #pragma unroll
    for (int ks = 0; ks < 4; ks++) {
        uint32_t acb = ((uint32_t)(ks * 32) + a_c16) ^ xm;
        uint32_t bcb = ((uint32_t)(ks * 32) + b_c16) ^ xm;
        uint32_t af[2][4], bh[4][4], bl[4][4];
        #pragma unroll
        for (int mt = 0; mt < 2; mt++)
            ldsm4(af[mt][0], af[mt][1], af[mt][2], af[mt][3], aHi + arow[mt] + acb);
        #pragma unroll
        for (int np = 0; np < 4; np++) {
            ldsm4(bh[np][0], bh[np][1], bh[np][2], bh[np][3], bHi + brow[np] + bcb);
            ldsm4(bl[np][0], bl[np][1], bl[np][2], bl[np][3], bLo + brow[np] + bcb);
        }
        #pragma unroll
        for (int np = 0; np < 4; np++)
            #pragma unroll
            for (int mt = 0; mt < 2; mt++) {
                mma16816(acc[mt][np * 2],     af[mt], bh[np][0], bh[np][1]);
                mma16816(acc[mt][np * 2 + 1], af[mt], bh[np][2], bh[np][3]);
            }
        #pragma unroll
        for (int np = 0; np < 4; np++)
            #pragma unroll
            for (int mt = 0; mt < 2; mt++) {
                mma16816(acc[mt][np * 2],     af[mt], bl[np][0], bl[np][1]);
                mma16816(acc[mt][np * 2 + 1], af[mt], bl[np][2], bl[np][3]);
            }
        #pragma unroll
        for (int mt = 0; mt < 2; mt++)
            ldsm4(af[mt][0], af[mt][1], af[mt][2], af[mt][3], aLo + arow[mt] + acb);
        #pragma unroll
        for (int np = 0; np < 4; np++)
            #pragma unroll
            for (int mt = 0; mt < 2; mt++) {
                mma16816(acc[mt][np * 2],     af[mt], bh[np][0], bh[np][1]);
                mma16816(acc[mt][np * 2 + 1], af[mt], bh[np][2], bh[np][3]);
            }
    }
}

// SMEM: A stages 3x32KB @0 | B 128KB @98304 | bias 2KB @229376
#define SM_B    98304u
#define SM_BIAS 229376u
#define SM_DYN  231552

// ---------------------------------------------------------------------------
// Weight prep: As=(cw^T+wr)/2 (sel 0), Ad=(cw^T+wi)/2 (sel 1) -> hi/lo SW128
// ---------------------------------------------------------------------------
__global__ void prep_w_kernel(const float* __restrict__ wr,
                              const float* __restrict__ wi,
                              const float* __restrict__ cw,
                              unsigned short* __restrict__ wimg)
{
    int idx = blockIdx.x * blockDim.x + threadIdx.x;   // < 131072
    int l = idx >> 15;
    int rem = idx & 32767;
    int sel = rem >> 14;
    int rem2 = rem & 16383;
    int kc2 = rem2 >> 13;
    int rem3 = rem2 & 8191;
    int o = rem3 >> 6;
    int kl = rem3 & 63;
    int k = kc2 * 64 + kl;
    const float* wsel = (sel ? wi : wr) + (size_t)l * 16384;
    float v = 0.5f * (cw[(size_t)l * 16384 + o * 128 + k] + wsel[k * 128 + o]);
    uint32_t u = __float_as_uint(v);
    float hf = __uint_as_float(u & 0xffff0000u);
    float lo = v - hf;
    uint32_t off = (uint32_t)o * 128 + kl * 2;
    off ^= (off >> 3) & 0x70;
    size_t base = (size_t)l * 65536 + sel * 32768 + kc2 * 8192;
    wimg[base + (off >> 1)] = (unsigned short)(u >> 16);
    __nv_bfloat16 lb = __float2bfloat16_rn(lo);
    wimg[base + 16384 + (off >> 1)] = __bfloat16_as_ushort(lb);
}

__global__ void prep_sx_kernel(float* __restrict__ sx)
{
    int x = threadIdx.x;
    double s = 0.0;
    if (x) {
        double th = M_PI * (double)x / 128.0;
        s = sin(63.5 * th) * sin(64.0 * th) / sin(0.5 * th);
    }
    sx[x] = (float)(-s / 128.0);
}

// ---------------------------------------------------------------------------
// Input transform -> canonical s/d bf16 hi/lo
// ---------------------------------------------------------------------------
__global__ void in_kernel(const float* __restrict__ x,
                          const float* __restrict__ w,
                          const float* __restrict__ bias,
                          unsigned short* __restrict__ act)
{
    int gid = blockIdx.x * blockDim.x + threadIdx.x;
    int slot = gid >> 5;
    int c4 = (gid & 31) << 2;
    int t = slot >> 7, m = slot & 127;
    int b = t / TPI, tt = t - b * TPI;
    int r, x0;
    decode_ctile(tt, r, x0);
    int xc = x0 + m;
    int rf = (256 - r) & 255, xf = (256 - xc) & 255;
    const float* xb = x + (size_t)b * 196608;
    int ip = r * 256 + xc, iq = rf * 256 + xf;
    float xp0 = __ldg(xb + ip), xp1 = __ldg(xb + ip + 65536), xp2 = __ldg(xb + ip + 131072);
    float xq0 = __ldg(xb + iq), xq1 = __ldg(xb + iq + 65536), xq2 = __ldg(xb + iq + 131072);
    float4 w0 = __ldg((const float4*)(w + c4));
    float4 w1 = __ldg((const float4*)(w + 128 + c4));
    float4 w2 = __ldg((const float4*)(w + 256 + c4));
    float4 bb = __ldg((const float4*)(bias + c4));
    float gp0 = gelu_exact(xp0 * w0.x + xp1 * w1.x + xp2 * w2.x + bb.x);
    float gp1 = gelu_exact(xp0 * w0.y + xp1 * w1.y + xp2 * w2.y + bb.y);
    float gp2 = gelu_exact(xp0 * w0.z + xp1 * w1.z + xp2 * w2.z + bb.z);
    float gp3 = gelu_exact(xp0 * w0.w + xp1 * w1.w + xp2 * w2.w + bb.w);
    float gf0 = gelu_exact(xq0 * w0.x + xq1 * w1.x + xq2 * w2.x + bb.x);
    float gf1 = gelu_exact(xq0 * w0.y + xq1 * w1.y + xq2 * w2.y + bb.y);
    float gf2 = gelu_exact(xq0 * w0.z + xq1 * w1.z + xq2 * w2.z + bb.z);
    float gf3 = gelu_exact(xq0 * w0.w + xq1 * w1.w + xq2 * w2.w + bb.w);
    float s0 = gp0 + gf0, s1 = gp1 + gf1, s2 = gp2 + gf2, s3 = gp3 + gf3;
    float d0 = gp0 - gf0, d1 = gp1 - gf1, d2 = gp2 - gf2, d3 = gp3 - gf3;
    size_t wb = (size_t)slot * 64 + (c4 >> 1);
    uint32_t* aSH = (uint32_t*)act;
    uint32_t* aSL = aSH + (PART >> 1);
    uint32_t* aDH = aSH + PART;
    uint32_t* aDL = aDH + (PART >> 1);
    uint2 v;
    v.x = pack_hi2(s0, s1); v.y = pack_hi2(s2, s3); *(uint2*)(aSH + wb) = v;
    v.x = pack_lo2(s0, s1); v.y = pack_lo2(s2, s3); *(uint2*)(aSL + wb) = v;
    v.x = pack_hi2(d0, d1); v.y = pack_hi2(d2, d3); *(uint2*)(aDH + wb) = v;
    v.x = pack_lo2(d0, d1); v.y = pack_lo2(d2, d3); *(uint2*)(aDL + wb) = v;
}

// ---------------------------------------------------------------------------
// Layer kernel: 256 thr / 8 warps, warp tile 32m x 64n, P/Q pair GEMM
// ---------------------------------------------------------------------------
__global__ void __launch_bounds__(THREADS, 1) layer_kernel(
    const unsigned short* __restrict__ actIn,
    unsigned short* __restrict__ actOut,
    const uint4* __restrict__ wimgL,
    const float* __restrict__ cbp, const float* __restrict__ brp,
    const float* __restrict__ bip, const float* __restrict__ lowp,
    const float* __restrict__ lobp, float* __restrict__ gout, int fuse)
{
    extern __shared__ char dsm_raw[];
    uint32_t raw = smem_u32(dsm_raw);
    uint32_t sbase = (raw + 127) & ~127u;
    char* sm = dsm_raw + (sbase - raw);

    int tid = threadIdx.x, wid = tid >> 5, lane = tid & 31;
    int wm = wid & 3, wn = wid >> 2;     // 4 m-groups x 32, 2 n-groups x 64

    // cp.async mapping: m = tid>>1 row, q = tid&1 half-row (64B each)
    int m = tid >> 1, q = tid & 1;
    uint32_t swz = (uint32_t)(m & 7) << 4;
    uint32_t offA[4];
    #pragma unroll
    for (int j = 0; j < 4; j++)
        offA[j] = (uint32_t)m * 128u + ((((uint32_t)q * 64u) + (uint32_t)j * 16u) ^ swz);

    size_t thOff = ((size_t)blockIdx.x * 128 + m) * 128 + q * 32;
    const unsigned short* pSH = actIn + thOff;
    const unsigned short* pSL = pSH + PART;
    const unsigned short* pDH = pSH + 2 * (size_t)PART;
    const unsigned short* pDL = pSH + 3 * (size_t)PART;
    const size_t TSTR = (size_t)GRID * 16384;

    int nloc = (NTILE_TOT - blockIdx.x + GRID - 1) / GRID;

    uint32_t stI = 0;
    #define ISSUE4(PH, PL, K0) do { \
        uint32_t stb = sbase + stI * 32768u; \
        CP16(stb + offA[0], (PH) + (K0));      CP16(stb + offA[1], (PH) + (K0) + 8); \
        CP16(stb + offA[2], (PH) + (K0) + 16); CP16(stb + offA[3], (PH) + (K0) + 24); \
        CP16(stb + 16384u + offA[0], (PL) + (K0));      CP16(stb + 16384u + offA[1], (PL) + (K0) + 8); \
        CP16(stb + 16384u + offA[2], (PL) + (K0) + 16); CP16(stb + 16384u + offA[3], (PL) + (K0) + 24); \
        CP_COMMIT(); stI = (stI == 2) ? 0 : stI + 1; } while (0)
    #define ISSUE_NONE() do { CP_COMMIT(); stI = (stI == 2) ? 0 : stI + 1; } while (0)

    ISSUE4(pSH, pSL, 0);
    ISSUE4(pSH, pSL, 64);
    {
        uint4* bs = (uint4*)(sm + SM_B);
        #pragma unroll
        for (int qq = 0; qq < 32; qq++)
            bs[tid + qq * 256] = __ldg(wimgL + tid + qq * 256);
        float* bf = (float*)(sm + SM_BIAS);
        if (tid < 128) {
            bf[tid]       = __ldg(cbp + tid);
            bf[128 + tid] = __ldg(brp + tid);
            bf[256 + tid] = __ldg(bip + tid);
            bf[384 + tid] = __ldg(lowp + tid);
        }
    }
    __syncthreads();

    int grp = lane >> 3, lr = lane & 7;
    uint32_t xm = (uint32_t)(lr << 4);
    uint32_t a_c16 = (uint32_t)((grp >> 1) << 4);
    uint32_t b_c16 = (uint32_t)((grp & 1) << 4);
    uint32_t arow[2], brow[4];
    #pragma unroll
    for (int mt = 0; mt < 2; mt++)
        arow[mt] = (uint32_t)(wm * 32 + mt * 16 + lr + ((grp & 1) << 3)) * 128u;
    #pragma unroll
    for (int np = 0; np < 4; np++)
        brow[np] = (uint32_t)(wn * 64 + np * 16 + lr + ((grp >> 1) << 3)) * 128u;

    const float* cbS  = (const float*)(sm + SM_BIAS);
    const float* brS  = cbS + 128;
    const float* biS  = cbS + 256;
    const float* lowS = cbS + 384;

    uint32_t stM = 0;
    for (int i = 0; i < nloc; i++) {
        int t = blockIdx.x + i * GRID;
        int b = t / TPI, tt = t - b * TPI;
        int r, x0;
        decode_ctile(tt, r, x0);
        bool haveNext = (i + 1 < nloc);
        bool row0 = (r == 0);

        float accP[2][8][4], accQ[2][8][4];
        #pragma unroll
        for (int mt = 0; mt < 2; mt++)
            #pragma unroll
            for (int nt = 0; nt < 8; nt++)
                #pragma unroll
                for (int z = 0; z < 4; z++) { accP[mt][nt][z] = 0.0f; accQ[mt][nt][z] = 0.0f; }

        CP_WAIT1(); __syncthreads();
        ISSUE4(pDH, pDL, 0);
        mma_chunk(accP, sbase + stM * 32768u, sbase + SM_B, arow, brow, a_c16, b_c16, xm);
        stM = (stM == 2) ? 0 : stM + 1;

        CP_WAIT1(); __syncthreads();
        ISSUE4(pDH, pDL, 64);
        mma_chunk(accP, sbase + stM * 32768u, sbase + SM_B + 16384u, arow, brow, a_c16, b_c16, xm);
        stM = (stM == 2) ? 0 : stM + 1;

        CP_WAIT1(); __syncthreads();
        if (haveNext) ISSUE4(pSH + TSTR, pSL + TSTR, 0); else ISSUE_NONE();
        mma_chunk(accQ, sbase + stM * 32768u, sbase + SM_B + 65536u, arow, brow, a_c16, b_c16, xm);
        stM = (stM == 2) ? 0 : stM + 1;

        CP_WAIT1(); __syncthreads();
        if (haveNext) ISSUE4(pSH + TSTR, pSL + TSTR, 64); else ISSUE_NONE();
        uint32_t stEpi = stM;
        mma_chunk(accQ, sbase + stM * 32768u, sbase + SM_B + 81920u, arow, brow, a_c16, b_c16, xm);
        stM = (stM == 2) ? 0 : stM + 1;

        if (!fuse) {
            uint32_t* oSH = (uint32_t*)actOut + (size_t)t * 8192;
            uint32_t* oSL = oSH + (PART >> 1);
            uint32_t* oDH = oSH + PART;
            uint32_t* oDL = oDH + (PART >> 1);
            #pragma unroll
            for (int mt = 0; mt < 2; mt++) {
                #pragma unroll
                for (int rh = 0; rh < 2; rh++) {
                    int mm = wm * 32 + mt * 16 + (lane >> 2) + rh * 8;
                    int xc = x0 + mm;
                    int xf = (256 - xc) & 255;
                    float sxp = row0 ? __ldg(&g_sx[xc]) : 0.0f;
                    float sxf = row0 ? __ldg(&g_sx[xf]) : 0.0f;
                    uint32_t ob = (uint32_t)mm * 64;
                    #pragma unroll
                    for (int nt = 0; nt < 8; nt++) {
                        int n = wn * 64 + nt * 8 + (lane & 3) * 2;
                        float P0 = accP[mt][nt][rh * 2], P1 = accP[mt][nt][rh * 2 + 1];
                        float Q0 = accQ[mt][nt][rh * 2], Q1 = accQ[mt][nt][rh * 2 + 1];
                        float c0 = cbS[n], c1 = cbS[n + 1];
                        float up0 = P0 + Q0 + c0, up1 = P1 + Q1 + c1;
                        float uf0 = P0 - Q0 + c0, uf1 = P1 - Q1 + c1;
                        if (row0) {
                            float b0 = biS[n], b1 = biS[n + 1];
                            up0 += b0 * sxp; up1 += b1 * sxp;
                            uf0 += b0 * sxf; uf1 += b1 * sxf;
                            if (xc == 0) {
                                up0 += brS[n]; up1 += brS[n + 1];
                                uf0 += brS[n]; uf1 += brS[n + 1];
                            }
                        }
                        float gp0 = gelu_exact(up0), gp1 = gelu_exact(up1);
                        float gf0 = gelu_exact(uf0), gf1 = gelu_exact(uf1);
                        float s0 = gp0 + gf0, s1 = gp1 + gf1;
                        float d0 = gp0 - gf0, d1 = gp1 - gf1;
                        uint32_t w = ob + (n >> 1);
                        oSH[w] = pack_hi2(s0, s1); oSL[w] = pack_lo2(s0, s1);
                        oDH[w] = pack_hi2(d0, d1); oDL[w] = pack_lo2(d0, d1);
                    }
                }
            }
        } else {
            float* red = (float*)(sm + stEpi * 32768u);
            float ppv[2][2], pfv[2][2];
            #pragma unroll
            for (int mt = 0; mt < 2; mt++) {
                #pragma unroll
                for (int rh = 0; rh < 2; rh++) {
                    int mm = wm * 32 + mt * 16 + (lane >> 2) + rh * 8;
                    int xc = x0 + mm;
                    int xf = (256 - xc) & 255;
                    float sxp = row0 ? __ldg(&g_sx[xc]) : 0.0f;
                    float sxf = row0 ? __ldg(&g_sx[xf]) : 0.0f;
                    float pp = 0.0f, pf = 0.0f;
                    #pragma unroll
                    for (int nt = 0; nt < 8; nt++) {
                        int n = wn * 64 + nt * 8 + (lane & 3) * 2;
                        float P0 = accP[mt][nt][rh * 2], P1 = accP[mt][nt][rh * 2 + 1];
                        float Q0 = accQ[mt][nt][rh * 2], Q1 = accQ[mt][nt][rh * 2 + 1];
                        float c0 = cbS[n], c1 = cbS[n + 1];
                        float up0 = P0 + Q0 + c0, up1 = P1 + Q1 + c1;
                        float uf0 = P0 - Q0 + c0, uf1 = P1 - Q1 + c1;
                        if (row0) {
                            float b0 = biS[n], b1 = biS[n + 1];
                            up0 += b0 * sxp; up1 += b1 * sxp;
                            uf0 += b0 * sxf; uf1 += b1 * sxf;
                            if (xc == 0) {
                                up0 += brS[n]; up1 += brS[n + 1];
                                uf0 += brS[n]; uf1 += brS[n + 1];
                            }
                        }
                        pp += gelu_exact(up0) * lowS[n] + gelu_exact(up1) * lowS[n + 1];
                        pf += gelu_exact(uf0) * lowS[n] + gelu_exact(uf1) * lowS[n + 1];
                    }
                    pp += __shfl_xor_sync(0xffffffffu, pp, 1);
                    pp += __shfl_xor_sync(0xffffffffu, pp, 2);
                    pf += __shfl_xor_sync(0xffffffffu, pf, 1);
                    pf += __shfl_xor_sync(0xffffffffu, pf, 2);
                    ppv[mt][rh] = pp; pfv[mt][rh] = pf;
                }
            }
            __syncthreads();
            if ((lane & 3) == 0) {
                #pragma unroll
                for (int mt = 0; mt < 2; mt++)
                    #pragma unroll
                    for (int rh = 0; rh < 2; rh++) {
                        int mm = wm * 32 + mt * 16 + (lane >> 2) + rh * 8;
                        red[wn * 128 + mm] = ppv[mt][rh];
                        red[256 + wn * 128 + mm] = pfv[mt][rh];
                    }
            }
            __syncthreads();
            if (tid < 128) {
                float lob = __ldg(lobp);
                float sp = red[tid] + red[128 + tid];
                float sf = red[256 + tid] + red[384 + tid];
                int xc = x0 + tid, xf = (256 - xc) & 255, rf = (256 - r) & 255;
                gout[(size_t)b * 65536 + r * 256 + xc]  = gelu_exact(sp + lob);
                gout[(size_t)b * 65536 + rf * 256 + xf] = gelu_exact(sf + lob);
            }
            __syncthreads();
        }
        pSH += TSTR; pSL += TSTR; pDH += TSTR; pDL += TSTR;
    }
}

// ---------------------------------------------------------------------------
extern "C" void kernel_launch(void* const* d_in, const int* in_sizes, int n_in,
                              void* d_out, int out_size)
{
    const float* x   = (const float*)d_in[0];
    const float* liw = (const float*)d_in[1];
    const float* lib = (const float*)d_in[2];
    const float* wr  = (const float*)d_in[3];
    const float* wi  = (const float*)d_in[4];
    const float* br  = (const float*)d_in[5];
    const float* bi  = (const float*)d_in[6];
    const float* cw  = (const float*)d_in[7];
    const float* cb  = (const float*)d_in[8];
    const float* low = (const float*)d_in[9];
    const float* lob = (const float*)d_in[10];
    float* out = (float*)d_out;

    unsigned short *a0, *a1, *wimg;
    float* sx;
    cudaGetSymbolAddress((void**)&a0, g_act0);
    cudaGetSymbolAddress((void**)&a1, g_act1);
    cudaGetSymbolAddress((void**)&wimg, g_wimg);
    cudaGetSymbolAddress((void**)&sx, g_sx);

    cudaFuncSetAttribute(layer_kernel, cudaFuncAttributeMaxDynamicSharedMemorySize, SM_DYN);

    prep_w_kernel<<<512, 256>>>(wr, wi, cw, wimg);
    prep_sx_kernel<<<1, 256>>>(sx);
    in_kernel<<<NTILE_TOT * 128 * 32 / 256, 256>>>(x, liw, lib, a0);

    unsigned short* as[2] = { a0, a1 };
    for (int l = 0; l < NL; l++) {
        int fuse = (l == NL - 1) ? 1 : 0;
        layer_kernel<<<GRID, THREADS, SM_DYN>>>(
            as[l & 1], as[(l & 1) ^ 1],
            (const uint4*)(wimg + (size_t)l * 65536),
            cb + l * HID, br + l * HID, bi + l * HID,
            low, lob, out, fuse);
    }
}

// round 13
// speedup vs baseline: 1.1784x; 1.1784x over previous
#include <cuda_runtime.h>
#include <cuda_bf16.h>
#include <math.h>
#include <stdint.h>

#define HID 128
#define NL 4
#define TPI 258
#define NTILE_TOT (TPI*4)          // 1032 canonical tiles
#define NHT (NTILE_TOT*2)          // 2064 half-tiles
#define GRID 152
#define THREADS 512
#define PART 16908288              // 1032*128*128 elements per component

__device__ unsigned short g_act0[4*(size_t)PART];
__device__ unsigned short g_act1[4*(size_t)PART];
__device__ unsigned short g_wimg[NL * 65536];
__device__ float g_sx[256];

__device__ __forceinline__ uint32_t smem_u32(const void* p) {
    uint32_t a;
    asm("{ .reg .u64 t; cvta.to.shared.u64 t, %1; cvt.u32.u64 %0, t; }" : "=r"(a) : "l"(p));
    return a;
}
__device__ __forceinline__ void ldsm4(uint32_t& r0, uint32_t& r1, uint32_t& r2, uint32_t& r3, uint32_t addr) {
    asm volatile("ldmatrix.sync.aligned.m8n8.x4.shared.b16 {%0,%1,%2,%3}, [%4];"
        : "=r"(r0), "=r"(r1), "=r"(r2), "=r"(r3) : "r"(addr));
}
__device__ __forceinline__ void mma16816(float* d, const uint32_t* a, uint32_t b0, uint32_t b1) {
    asm volatile("mma.sync.aligned.m16n8k16.row.col.f32.bf16.bf16.f32 "
        "{%0,%1,%2,%3}, {%4,%5,%6,%7}, {%8,%9}, {%0,%1,%2,%3};"
        : "+f"(d[0]), "+f"(d[1]), "+f"(d[2]), "+f"(d[3])
        : "r"(a[0]), "r"(a[1]), "r"(a[2]), "r"(a[3]), "r"(b0), "r"(b1));
}
#define CP16(dst, src) asm volatile("cp.async.cg.shared.global [%0], [%1], 16;" :: "r"(dst), "l"(src))
#define CP_COMMIT()    asm volatile("cp.async.commit_group;" ::: "memory")
#define CP_WAIT1()     asm volatile("cp.async.wait_group 1;" ::: "memory")
#define GBAR(gid)      asm volatile("bar.sync %0, 256;" :: "r"((gid) + 1) : "memory")

__device__ __forceinline__ float gelu_exact(float v) {
    return 0.5f * v * (1.0f + erff(v * 0.70710678118654752f));
}
__device__ __forceinline__ uint32_t pack_hi2(float a, float b) {
    return __byte_perm(__float_as_uint(a), __float_as_uint(b), 0x7632);
}
__device__ __forceinline__ uint32_t pack_lo2(float a, float b) {
    float ra = a - __uint_as_float(__float_as_uint(a) & 0xffff0000u);
    float rb = b - __uint_as_float(__float_as_uint(b) & 0xffff0000u);
    __nv_bfloat162 p = __floats2bfloat162_rn(ra, rb);
    return *reinterpret_cast<uint32_t*>(&p);
}
__device__ __forceinline__ void decode_ctile(int tt, int& r, int& x0) {
    if (tt < 254)      { r = 1 + (tt >> 1); x0 = (tt & 1) << 7; }
    else if (tt < 256) { r = 0;             x0 = (tt - 254) << 7; }
    else               { r = 128;           x0 = (tt - 256) << 7; }
}

// one k64 chunk of one GEMM bank: 64m x 32n warp tiles, 3-combo bf16 split
// A stage: hi 8KB (64 rows x 128B) + lo at +8192
__device__ __forceinline__ void mma_chunk(
    float (&acc)[2][4][4], uint32_t aHi, uint32_t bHi,
    const uint32_t (&arow)[2], const uint32_t (&brow)[2],
    uint32_t a_c16, uint32_t b_c16, uint32_t xm)
{
    uint32_t aLo = aHi + 8192u;
    uint32_t bLo = bHi + 32768u;
    #pragma unroll
    for (int ks = 0; ks < 4; ks++) {
        uint32_t acb = ((uint32_t)(ks * 32) + a_c16) ^ xm;
        uint32_t bcb = ((uint32_t)(ks * 32) + b_c16) ^ xm;
        uint32_t af[2][4], bh[2][4], bl[2][4];
        #pragma unroll
        for (int mt = 0; mt < 2; mt++)
            ldsm4(af[mt][0], af[mt][1], af[mt][2], af[mt][3], aHi + arow[mt] + acb);
        #pragma unroll
        for (int np = 0; np < 2; np++) {
            ldsm4(bh[np][0], bh[np][1], bh[np][2], bh[np][3], bHi + brow[np] + bcb);
            ldsm4(bl[np][0], bl[np][1], bl[np][2], bl[np][3], bLo + brow[np] + bcb);
        }
        #pragma unroll
        for (int np = 0; np < 2; np++)
            #pragma unroll
            for (int mt = 0; mt < 2; mt++) {
                mma16816(acc[mt][np * 2],     af[mt], bh[np][0], bh[np][1]);
                mma16816(acc[mt][np * 2 + 1], af[mt], bh[np][2], bh[np][3]);
            }
        #pragma unroll
        for (int np = 0; np < 2; np++)
            #pragma unroll
            for (int mt = 0; mt < 2; mt++) {
                mma16816(acc[mt][np * 2],     af[mt], bl[np][0], bl[np][1]);
                mma16816(acc[mt][np * 2 + 1], af[mt], bl[np][2], bl[np][3]);
            }
        #pragma unroll
        for (int mt = 0; mt < 2; mt++)
            ldsm4(af[mt][0], af[mt][1], af[mt][2], af[mt][3], aLo + arow[mt] + acb);
        #pragma unroll
        for (int np = 0; np < 2; np++)
            #pragma unroll
            for (int mt = 0; mt < 2; mt++) {
                mma16816(acc[mt][np * 2],     af[mt], bh[np][0], bh[np][1]);
                mma16816(acc[mt][np * 2 + 1], af[mt], bh[np][2], bh[np][3]);
            }
    }
}

// SMEM: A stages 2 groups x 3 x 16KB @0 | B 128KB @98304 | bias 2KB @229376
#define SM_B    98304u
#define SM_BIAS 229376u
#define SM_DYN  231424

// ---------------------------------------------------------------------------
// Weight prep: As=(cw^T+wr)/2 (sel 0), Ad=(cw^T+wi)/2 (sel 1) -> hi/lo SW128
// ---------------------------------------------------------------------------
__global__ void prep_w_kernel(const float* __restrict__ wr,
                              const float* __restrict__ wi,
                              const float* __restrict__ cw,
                              unsigned short* __restrict__ wimg)
{
    int idx = blockIdx.x * blockDim.x + threadIdx.x;   // < 131072
    int l = idx >> 15;
    int rem = idx & 32767;
    int sel = rem >> 14;
    int rem2 = rem & 16383;
    int kc2 = rem2 >> 13;
    int rem3 = rem2 & 8191;
    int o = rem3 >> 6;
    int kl = rem3 & 63;
    int k = kc2 * 64 + kl;
    const float* wsel = (sel ? wi : wr) + (size_t)l * 16384;
    float v = 0.5f * (cw[(size_t)l * 16384 + o * 128 + k] + wsel[k * 128 + o]);
    uint32_t u = __float_as_uint(v);
    float hf = __uint_as_float(u & 0xffff0000u);
    float lo = v - hf;
    uint32_t off = (uint32_t)o * 128 + kl * 2;
    off ^= (off >> 3) & 0x70;
    size_t base = (size_t)l * 65536 + sel * 32768 + kc2 * 8192;
    wimg[base + (off >> 1)] = (unsigned short)(u >> 16);
    __nv_bfloat16 lb = __float2bfloat16_rn(lo);
    wimg[base + 16384 + (off >> 1)] = __bfloat16_as_ushort(lb);
}

__global__ void prep_sx_kernel(float* __restrict__ sx)
{
    int x = threadIdx.x;
    double s = 0.0;
    if (x) {
        double th = M_PI * (double)x / 128.0;
        s = sin(63.5 * th) * sin(64.0 * th) / sin(0.5 * th);
    }
    sx[x] = (float)(-s / 128.0);
}

// ---------------------------------------------------------------------------
// Input transform -> canonical s/d bf16 hi/lo
// ---------------------------------------------------------------------------
__global__ void in_kernel(const float* __restrict__ x,
                          const float* __restrict__ w,
                          const float* __restrict__ bias,
                          unsigned short* __restrict__ act)
{
    int gid = blockIdx.x * blockDim.x + threadIdx.x;
    int slot = gid >> 5;
    int c4 = (gid & 31) << 2;
    int t = slot >> 7, m = slot & 127;
    int b = t / TPI, tt = t - b * TPI;
    int r, x0;
    decode_ctile(tt, r, x0);
    int xc = x0 + m;
    int rf = (256 - r) & 255, xf = (256 - xc) & 255;
    const float* xb = x + (size_t)b * 196608;
    int ip = r * 256 + xc, iq = rf * 256 + xf;
    float xp0 = __ldg(xb + ip), xp1 = __ldg(xb + ip + 65536), xp2 = __ldg(xb + ip + 131072);
    float xq0 = __ldg(xb + iq), xq1 = __ldg(xb + iq + 65536), xq2 = __ldg(xb + iq + 131072);
    float4 w0 = __ldg((const float4*)(w + c4));
    float4 w1 = __ldg((const float4*)(w + 128 + c4));
    float4 w2 = __ldg((const float4*)(w + 256 + c4));
    float4 bb = __ldg((const float4*)(bias + c4));
    float gp0 = gelu_exact(xp0 * w0.x + xp1 * w1.x + xp2 * w2.x + bb.x);
    float gp1 = gelu_exact(xp0 * w0.y + xp1 * w1.y + xp2 * w2.y + bb.y);
    float gp2 = gelu_exact(xp0 * w0.z + xp1 * w1.z + xp2 * w2.z + bb.z);
    float gp3 = gelu_exact(xp0 * w0.w + xp1 * w1.w + xp2 * w2.w + bb.w);
    float gf0 = gelu_exact(xq0 * w0.x + xq1 * w1.x + xq2 * w2.x + bb.x);
    float gf1 = gelu_exact(xq0 * w0.y + xq1 * w1.y + xq2 * w2.y + bb.y);
    float gf2 = gelu_exact(xq0 * w0.z + xq1 * w1.z + xq2 * w2.z + bb.z);
    float gf3 = gelu_exact(xq0 * w0.w + xq1 * w1.w + xq2 * w2.w + bb.w);
    float s0 = gp0 + gf0, s1 = gp1 + gf1, s2 = gp2 + gf2, s3 = gp3 + gf3;
    float d0 = gp0 - gf0, d1 = gp1 - gf1, d2 = gp2 - gf2, d3 = gp3 - gf3;
    size_t wb = (size_t)slot * 64 + (c4 >> 1);
    uint32_t* aSH = (uint32_t*)act;
    uint32_t* aSL = aSH + (PART >> 1);
    uint32_t* aDH = aSH + PART;
    uint32_t* aDL = aDH + (PART >> 1);
    uint2 v;
    v.x = pack_hi2(s0, s1); v.y = pack_hi2(s2, s3); *(uint2*)(aSH + wb) = v;
    v.x = pack_lo2(s0, s1); v.y = pack_lo2(s2, s3); *(uint2*)(aSL + wb) = v;
    v.x = pack_hi2(d0, d1); v.y = pack_hi2(d2, d3); *(uint2*)(aDH + wb) = v;
    v.x = pack_lo2(d0, d1); v.y = pack_lo2(d2, d3); *(uint2*)(aDL + wb) = v;
}

// ---------------------------------------------------------------------------
// Layer kernel: two independent 8-warp groups per CTA, 64-row half-tiles
// ---------------------------------------------------------------------------
__global__ void __launch_bounds__(THREADS, 1) layer_kernel(
    const unsigned short* __restrict__ actIn,
    unsigned short* __restrict__ actOut,
    const uint4* __restrict__ wimgL,
    const float* __restrict__ cbp, const float* __restrict__ brp,
    const float* __restrict__ bip, const float* __restrict__ lowp,
    const float* __restrict__ lobp, float* __restrict__ gout, int fuse)
{
    extern __shared__ char dsm_raw[];
    uint32_t raw = smem_u32(dsm_raw);
    uint32_t sbase = (raw + 127) & ~127u;
    char* sm = dsm_raw + (sbase - raw);

    int tid = threadIdx.x, wid = tid >> 5, lane = tid & 31;
    int g = wid >> 3;            // group 0/1
    int widg = wid & 7;
    int tidg = tid & 255;
    int wm = widg & 1;           // 2 m-groups x 32 (within 64-row half-tile)
    int wn = widg >> 1;          // 4 n-groups x 32

    // cp.async mapping within group: rowg = tidg>>2 (64 rows), q = tidg&3
    int rowg = tidg >> 2, q = tidg & 3;
    uint32_t swz = (uint32_t)(rowg & 7) << 4;
    uint32_t off0 = (uint32_t)rowg * 128u + (((uint32_t)q * 32u) ^ swz);
    uint32_t off1 = (uint32_t)rowg * 128u + (((uint32_t)q * 32u + 16u) ^ swz);
    uint32_t gsb = sbase + (uint32_t)g * 49152u;   // group stage base

    int start = blockIdx.x + g * GRID;             // half-tile stream start
    int nloc = (NHT - start + 303) / 304;

    // per-thread A pointers for current half-tile stream
    size_t slotBase = ((size_t)(start >> 1)) * 128 + (size_t)(start & 1) * 64;
    size_t thOff = (slotBase + rowg) * 128 + q * 16;
    const unsigned short* pSH = actIn + thOff;
    const unsigned short* pSL = pSH + PART;
    const unsigned short* pDH = pSH + 2 * (size_t)PART;
    const unsigned short* pDL = pSH + 3 * (size_t)PART;
    const size_t TSTR = (size_t)GRID * 128 * 128;  // slot stride 152*128 elements *128ch

    uint32_t stI = 0;
    #define ISSUE4(PH, PL, K0) do { \
        uint32_t stb = gsb + stI * 16384u; \
        CP16(stb + off0, (PH) + (K0));           CP16(stb + off1, (PH) + (K0) + 8); \
        CP16(stb + 8192u + off0, (PL) + (K0));   CP16(stb + 8192u + off1, (PL) + (K0) + 8); \
        CP_COMMIT(); stI = (stI == 2) ? 0 : stI + 1; } while (0)
    #define ISSUE_NONE() do { CP_COMMIT(); stI = (stI == 2) ? 0 : stI + 1; } while (0)

    ISSUE4(pSH, pSL, 0);
    ISSUE4(pSH, pSL, 64);
    {
        uint4* bs = (uint4*)(sm + SM_B);
        #pragma unroll
        for (int qq = 0; qq < 16; qq++)
            bs[tid + qq * 512] = __ldg(wimgL + tid + qq * 512);
        float* bf = (float*)(sm + SM_BIAS);
        if (tid < 128) {
            bf[tid]       = __ldg(cbp + tid);
            bf[128 + tid] = __ldg(brp + tid);
            bf[256 + tid] = __ldg(bip + tid);
            bf[384 + tid] = __ldg(lowp + tid);
        }
    }
    __syncthreads();
    if (g == 1) __nanosleep(1000);   // seed anti-aligned group phase

    // ldsm lane constants
    int grp = lane >> 3, lr = lane & 7;
    uint32_t xm = (uint32_t)(lr << 4);
    uint32_t a_c16 = (uint32_t)((grp >> 1) << 4);
    uint32_t b_c16 = (uint32_t)((grp & 1) << 4);
    uint32_t arow[2], brow[2];
    #pragma unroll
    for (int mt = 0; mt < 2; mt++)
        arow[mt] = (uint32_t)(wm * 32 + mt * 16 + lr + ((grp & 1) << 3)) * 128u;
    #pragma unroll
    for (int np = 0; np < 2; np++)
        brow[np] = (uint32_t)(wn * 32 + np * 16 + lr + ((grp >> 1) << 3)) * 128u;

    const float* cbS  = (const float*)(sm + SM_BIAS);
    const float* brS  = cbS + 128;
    const float* biS  = cbS + 256;
    const float* lowS = cbS + 384;

    uint32_t stM = 0;
    for (int i = 0; i < nloc; i++) {
        int ght = start + i * 304;
        int t = ght >> 1, half = ght & 1;
        int b = t / TPI, tt = t - b * TPI;
        int r, x0;
        decode_ctile(tt, r, x0);
        int x0h = x0 + half * 64;
        bool haveNext = (i + 1 < nloc);
        bool row0 = (r == 0);

        float accP[2][4][4], accQ[2][4][4];
        #pragma unroll
        for (int mt = 0; mt < 2; mt++)
            #pragma unroll
            for (int nt = 0; nt < 4; nt++)
                #pragma unroll
                for (int z = 0; z < 4; z++) { accP[mt][nt][z] = 0.0f; accQ[mt][nt][z] = 0.0f; }

        CP_WAIT1(); GBAR(g);
        ISSUE4(pDH, pDL, 0);
        mma_chunk(accP, gsb + stM * 16384u, sbase + SM_B, arow, brow, a_c16, b_c16, xm);
        stM = (stM == 2) ? 0 : stM + 1;

        CP_WAIT1(); GBAR(g);
        ISSUE4(pDH, pDL, 64);
        mma_chunk(accP, gsb + stM * 16384u, sbase + SM_B + 16384u, arow, brow, a_c16, b_c16, xm);
        stM = (stM == 2) ? 0 : stM + 1;

        CP_WAIT1(); GBAR(g);
        if (haveNext) ISSUE4(pSH + TSTR, pSL + TSTR, 0); else ISSUE_NONE();
        mma_chunk(accQ, gsb + stM * 16384u, sbase + SM_B + 65536u, arow, brow, a_c16, b_c16, xm);
        stM = (stM == 2) ? 0 : stM + 1;

        CP_WAIT1(); GBAR(g);
        if (haveNext) ISSUE4(pSH + TSTR, pSL + TSTR, 64); else ISSUE_NONE();
        uint32_t stEpi = stM;
        mma_chunk(accQ, gsb + stM * 16384u, sbase + SM_B + 81920u, arow, brow, a_c16, b_c16, xm);
        stM = (stM == 2) ? 0 : stM + 1;

        size_t osBase = (size_t)t * 128 + half * 64;

        if (!fuse) {
            uint32_t* oSH = (uint32_t*)actOut;
            uint32_t* oSL = oSH + (PART >> 1);
            uint32_t* oDH = oSH + PART;
            uint32_t* oDL = oDH + (PART >> 1);
            #pragma unroll
            for (int mt = 0; mt < 2; mt++) {
                #pragma unroll
                for (int rh = 0; rh < 2; rh++) {
                    int mm = wm * 32 + mt * 16 + (lane >> 2) + rh * 8;
                    int xc = x0h + mm;
                    int xf = (256 - xc) & 255;
                    float sxp = row0 ? __ldg(&g_sx[xc]) : 0.0f;
                    float sxf = row0 ? __ldg(&g_sx[xf]) : 0.0f;
                    size_t ob = (osBase + mm) * 64;
                    #pragma unroll
                    for (int nt = 0; nt < 4; nt++) {
                        int n = wn * 32 + nt * 8 + (lane & 3) * 2;
                        float P0 = accP[mt][nt][rh * 2], P1 = accP[mt][nt][rh * 2 + 1];
                        float Q0 = accQ[mt][nt][rh * 2], Q1 = accQ[mt][nt][rh * 2 + 1];
                        float c0 = cbS[n], c1 = cbS[n + 1];
                        float up0 = P0 + Q0 + c0, up1 = P1 + Q1 + c1;
                        float uf0 = P0 - Q0 + c0, uf1 = P1 - Q1 + c1;
                        if (row0) {
                            float b0 = biS[n], b1 = biS[n + 1];
                            up0 += b0 * sxp; up1 += b1 * sxp;
                            uf0 += b0 * sxf; uf1 += b1 * sxf;
                            if (xc == 0) {
                                up0 += brS[n]; up1 += brS[n + 1];
                                uf0 += brS[n]; uf1 += brS[n + 1];
                            }
                        }
                        float gp0 = gelu_exact(up0), gp1 = gelu_exact(up1);
                        float gf0 = gelu_exact(uf0), gf1 = gelu_exact(uf1);
                        float s0 = gp0 + gf0, s1 = gp1 + gf1;
                        float d0 = gp0 - gf0, d1 = gp1 - gf1;
                        size_t w = ob + (n >> 1);
                        oSH[w] = pack_hi2(s0, s1); oSL[w] = pack_lo2(s0, s1);
                        oDH[w] = pack_hi2(d0, d1); oDL[w] = pack_lo2(d0, d1);
                    }
                }
            }
        } else {
            // fused final layer: red aliases this group's retired stage
            float* red = (float*)(sm + (uint32_t)g * 49152u + stEpi * 16384u);
            float ppv[2][2], pfv[2][2];
            #pragma unroll
            for (int mt = 0; mt < 2; mt++) {
                #pragma unroll
                for (int rh = 0; rh < 2; rh++) {
                    int mm = wm * 32 + mt * 16 + (lane >> 2) + rh * 8;
                    int xc = x0h + mm;
                    int xf = (256 - xc) & 255;
                    float sxp = row0 ? __ldg(&g_sx[xc]) : 0.0f;
                    float sxf = row0 ? __ldg(&g_sx[xf]) : 0.0f;
                    float pp = 0.0f, pf = 0.0f;
                    #pragma unroll
                    for (int nt = 0; nt < 4; nt++) {
                        int n = wn * 32 + nt * 8 + (lane & 3) * 2;
                        float P0 = accP[mt][nt][rh * 2], P1 = accP[mt][nt][rh * 2 + 1];
                        float Q0 = accQ[mt][nt][rh * 2], Q1 = accQ[mt][nt][rh * 2 + 1];
                        float c0 = cbS[n], c1 = cbS[n + 1];
                        float up0 = P0 + Q0 + c0, up1 = P1 + Q1 + c1;
                        float uf0 = P0 - Q0 + c0, uf1 = P1 - Q1 + c1;
                        if (row0) {
                            float b0 = biS[n], b1 = biS[n + 1];
                            up0 += b0 * sxp; up1 += b1 * sxp;
                            uf0 += b0 * sxf; uf1 += b1 * sxf;
                            if (xc == 0) {
                                up0 += brS[n]; up1 += brS[n + 1];
                                uf0 += brS[n]; uf1 += brS[n + 1];
                            }
                        }
                        pp += gelu_exact(up0) * lowS[n] + gelu_exact(up1) * lowS[n + 1];
                        pf += gelu_exact(uf0) * lowS[n] + gelu_exact(uf1) * lowS[n + 1];
                    }
                    pp += __shfl_xor_sync(0xffffffffu, pp, 1);
                    pp += __shfl_xor_sync(0xffffffffu, pp, 2);
                    pf += __shfl_xor_sync(0xffffffffu, pf, 1);
                    pf += __shfl_xor_sync(0xffffffffu, pf, 2);
                    ppv[mt][rh] = pp; pfv[mt][rh] = pf;
                }
            }
            GBAR(g);   // group's stage reads done; safe to alias as red
            if ((lane & 3) == 0) {
                #pragma unroll
                for (int mt = 0; mt < 2; mt++)
                    #pragma unroll
                    for (int rh = 0; rh < 2; rh++) {
                        int mm = wm * 32 + mt * 16 + (lane >> 2) + rh * 8;
                        red[wn * 64 + mm]       = ppv[mt][rh];
                        red[256 + wn * 64 + mm] = pfv[mt][rh];
                    }
            }
            GBAR(g);
            if (tidg < 64) {
                float lob = __ldg(lobp);
                float sp = red[tidg] + red[64 + tidg] + red[128 + tidg] + red[192 + tidg];
                float sf = red[256 + tidg] + red[320 + tidg] + red[384 + tidg] + red[448 + tidg];
                int xc = x0h + tidg, xf = (256 - xc) & 255, rf = (256 - r) & 255;
                gout[(size_t)b * 65536 + r * 256 + xc]  = gelu_exact(sp + lob);
                gout[(size_t)b * 65536 + rf * 256 + xf] = gelu_exact(sf + lob);
            }
        }
        pSH += TSTR; pSL += TSTR; pDH += TSTR; pDL += TSTR;
    }
}

// ---------------------------------------------------------------------------
extern "C" void kernel_launch(void* const* d_in, const int* in_sizes, int n_in,
                              void* d_out, int out_size)
{
    const float* x   = (const float*)d_in[0];
    const float* liw = (const float*)d_in[1];
    const float* lib = (const float*)d_in[2];
    const float* wr  = (const float*)d_in[3];
    const float* wi  = (const float*)d_in[4];
    const float* br  = (const float*)d_in[5];
    const float* bi  = (const float*)d_in[6];
    const float* cw  = (const float*)d_in[7];
    const float* cb  = (const float*)d_in[8];
    const float* low = (const float*)d_in[9];
    const float* lob = (const float*)d_in[10];
    float* out = (float*)d_out;

    unsigned short *a0, *a1, *wimg;
    float* sx;
    cudaGetSymbolAddress((void**)&a0, g_act0);
    cudaGetSymbolAddress((void**)&a1, g_act1);
    cudaGetSymbolAddress((void**)&wimg, g_wimg);
    cudaGetSymbolAddress((void**)&sx, g_sx);

    cudaFuncSetAttribute(layer_kernel, cudaFuncAttributeMaxDynamicSharedMemorySize, SM_DYN);

    prep_w_kernel<<<512, 256>>>(wr, wi, cw, wimg);
    prep_sx_kernel<<<1, 256>>>(sx);
    in_kernel<<<NTILE_TOT * 128 * 32 / 256, 256>>>(x, liw, lib, a0);

    unsigned short* as[2] = { a0, a1 };
    for (int l = 0; l < NL; l++) {
        int fuse = (l == NL - 1) ? 1 : 0;
        layer_kernel<<<GRID, THREADS, SM_DYN>>>(
            as[l & 1], as[(l & 1) ^ 1],
            (const uint4*)(wimg + (size_t)l * 65536),
            cb + l * HID, br + l * HID, bi + l * HID,
            low, lob, out, fuse);
    }
}

// round 14
// speedup vs baseline: 1.2550x; 1.0650x over previous
#include <cuda_runtime.h>
#include <cuda_bf16.h>
#include <math.h>
#include <stdint.h>

#define HID 128
#define NL 4
#define TPI 258
#define NTILE_TOT (TPI*4)          // 1032 canonical tiles
#define NHT (NTILE_TOT*2)          // 2064 half-tiles
#define GRID 152
#define THREADS 512
#define PART 16908288              // elements per component (1032*128*128)

// Activation buffers hold pre-swizzled 16KB bank images:
// [half-tile ht][bank: s-k0 | s-k1 | d-k0 | d-k1][hi 8KB | lo 8KB]
__device__ unsigned short g_act0[4*(size_t)PART];
__device__ unsigned short g_act1[4*(size_t)PART];
__device__ unsigned short g_wimg[NL * 65536];
__device__ float g_sx[256];

__device__ __forceinline__ uint32_t smem_u32(const void* p) {
    uint32_t a;
    asm("{ .reg .u64 t; cvta.to.shared.u64 t, %1; cvt.u32.u64 %0, t; }" : "=r"(a) : "l"(p));
    return a;
}
__device__ __forceinline__ void ldsm4(uint32_t& r0, uint32_t& r1, uint32_t& r2, uint32_t& r3, uint32_t addr) {
    asm volatile("ldmatrix.sync.aligned.m8n8.x4.shared.b16 {%0,%1,%2,%3}, [%4];"
        : "=r"(r0), "=r"(r1), "=r"(r2), "=r"(r3) : "r"(addr));
}
__device__ __forceinline__ void mma16816(float* d, const uint32_t* a, uint32_t b0, uint32_t b1) {
    asm volatile("mma.sync.aligned.m16n8k16.row.col.f32.bf16.bf16.f32 "
        "{%0,%1,%2,%3}, {%4,%5,%6,%7}, {%8,%9}, {%0,%1,%2,%3};"
        : "+f"(d[0]), "+f"(d[1]), "+f"(d[2]), "+f"(d[3])
        : "r"(a[0]), "r"(a[1]), "r"(a[2]), "r"(a[3]), "r"(b0), "r"(b1));
}
#define GBAR(gid) asm volatile("bar.sync %0, 256;" :: "r"((gid) + 1) : "memory")
#define MBAR_INIT(a, c) asm volatile("mbarrier.init.shared.b64 [%0], %1;" :: "r"(a), "r"(c) : "memory")
#define MBAR_EXPECT(a, b) asm volatile("mbarrier.arrive.expect_tx.shared.b64 _, [%0], %1;" :: "r"(a), "r"(b) : "memory")
#define BULK_G2S(dst, src, mb) asm volatile( \
    "cp.async.bulk.shared::cluster.global.mbarrier::complete_tx::bytes [%0], [%1], %2, [%3];" \
    :: "r"(dst), "l"(src), "r"(16384), "r"(mb) : "memory")
#define MBAR_WAIT(addr, par) do { \
    asm volatile("{\n\t.reg .pred P;\n\tWAITL_%=:\n\t" \
        "mbarrier.try_wait.parity.shared.b64 P, [%0], %1;\n\t" \
        "@P bra.uni WAITD_%=;\n\tbra.uni WAITL_%=;\n\tWAITD_%=:\n\t}" \
        :: "r"(addr), "r"(par) : "memory"); \
} while(0)

__device__ __forceinline__ float gelu_exact(float v) {
    return 0.5f * v * (1.0f + erff(v * 0.70710678118654752f));
}
__device__ __forceinline__ uint32_t pack_hi2(float a, float b) {
    return __byte_perm(__float_as_uint(a), __float_as_uint(b), 0x7632);
}
__device__ __forceinline__ uint32_t pack_lo2(float a, float b) {
    float ra = a - __uint_as_float(__float_as_uint(a) & 0xffff0000u);
    float rb = b - __uint_as_float(__float_as_uint(b) & 0xffff0000u);
    __nv_bfloat162 p = __floats2bfloat162_rn(ra, rb);
    return *reinterpret_cast<uint32_t*>(&p);
}
__device__ __forceinline__ void decode_ctile(int tt, int& r, int& x0) {
    if (tt < 254)      { r = 1 + (tt >> 1); x0 = (tt & 1) << 7; }
    else if (tt < 256) { r = 0;             x0 = (tt - 254) << 7; }
    else               { r = 128;           x0 = (tt - 256) << 7; }
}

// one k64 chunk of one GEMM bank: 64-row half-tile, warp tile 32m x 32n
__device__ __forceinline__ void mma_chunk(
    float (&acc)[2][4][4], uint32_t aHi, uint32_t bHi,
    const uint32_t (&arow)[2], const uint32_t (&brow)[2],
    uint32_t a_c16, uint32_t b_c16, uint32_t xm)
{
    uint32_t aLo = aHi + 8192u;
    uint32_t bLo = bHi + 32768u;
    #pragma unroll
    for (int ks = 0; ks < 4; ks++) {
        uint32_t acb = ((uint32_t)(ks * 32) + a_c16) ^ xm;
        uint32_t bcb = ((uint32_t)(ks * 32) + b_c16) ^ xm;
        uint32_t af[2][4], bh[2][4], bl[2][4];
        #pragma unroll
        for (int mt = 0; mt < 2; mt++)
            ldsm4(af[mt][0], af[mt][1], af[mt][2], af[mt][3], aHi + arow[mt] + acb);
        #pragma unroll
        for (int np = 0; np < 2; np++) {
            ldsm4(bh[np][0], bh[np][1], bh[np][2], bh[np][3], bHi + brow[np] + bcb);
            ldsm4(bl[np][0], bl[np][1], bl[np][2], bl[np][3], bLo + brow[np] + bcb);
        }
        #pragma unroll
        for (int np = 0; np < 2; np++)
            #pragma unroll
            for (int mt = 0; mt < 2; mt++) {
                mma16816(acc[mt][np * 2],     af[mt], bh[np][0], bh[np][1]);
                mma16816(acc[mt][np * 2 + 1], af[mt], bh[np][2], bh[np][3]);
            }
        #pragma unroll
        for (int np = 0; np < 2; np++)
            #pragma unroll
            for (int mt = 0; mt < 2; mt++) {
                mma16816(acc[mt][np * 2],     af[mt], bl[np][0], bl[np][1]);
                mma16816(acc[mt][np * 2 + 1], af[mt], bl[np][2], bl[np][3]);
            }
        #pragma unroll
        for (int mt = 0; mt < 2; mt++)
            ldsm4(af[mt][0], af[mt][1], af[mt][2], af[mt][3], aLo + arow[mt] + acb);
        #pragma unroll
        for (int np = 0; np < 2; np++)
            #pragma unroll
            for (int mt = 0; mt < 2; mt++) {
                mma16816(acc[mt][np * 2],     af[mt], bh[np][0], bh[np][1]);
                mma16816(acc[mt][np * 2 + 1], af[mt], bh[np][2], bh[np][3]);
            }
    }
}

// SMEM: A stages 2 groups x 3 x 16KB @0 | B 128KB @98304 | bias 2KB @229376
#define SM_B    98304u
#define SM_BIAS 229376u
#define SM_DYN  231424

// ---------------------------------------------------------------------------
__global__ void prep_w_kernel(const float* __restrict__ wr,
                              const float* __restrict__ wi,
                              const float* __restrict__ cw,
                              unsigned short* __restrict__ wimg)
{
    int idx = blockIdx.x * blockDim.x + threadIdx.x;   // < 131072
    int l = idx >> 15;
    int rem = idx & 32767;
    int sel = rem >> 14;
    int rem2 = rem & 16383;
    int kc2 = rem2 >> 13;
    int rem3 = rem2 & 8191;
    int o = rem3 >> 6;
    int kl = rem3 & 63;
    int k = kc2 * 64 + kl;
    const float* wsel = (sel ? wi : wr) + (size_t)l * 16384;
    float v = 0.5f * (cw[(size_t)l * 16384 + o * 128 + k] + wsel[k * 128 + o]);
    uint32_t u = __float_as_uint(v);
    float hf = __uint_as_float(u & 0xffff0000u);
    float lo = v - hf;
    uint32_t off = (uint32_t)o * 128 + kl * 2;
    off ^= (off >> 3) & 0x70;
    size_t base = (size_t)l * 65536 + sel * 32768 + kc2 * 8192;
    wimg[base + (off >> 1)] = (unsigned short)(u >> 16);
    __nv_bfloat16 lb = __float2bfloat16_rn(lo);
    wimg[base + 16384 + (off >> 1)] = __bfloat16_as_ushort(lb);
}

__global__ void prep_sx_kernel(float* __restrict__ sx)
{
    int x = threadIdx.x;
    double s = 0.0;
    if (x) {
        double th = M_PI * (double)x / 128.0;
        s = sin(63.5 * th) * sin(64.0 * th) / sin(0.5 * th);
    }
    sx[x] = (float)(-s / 128.0);
}

// ---------------------------------------------------------------------------
// Input transform -> pre-swizzled s/d bank images
// ---------------------------------------------------------------------------
__global__ void in_kernel(const float* __restrict__ x,
                          const float* __restrict__ w,
                          const float* __restrict__ bias,
                          unsigned short* __restrict__ act)
{
    int gid = blockIdx.x * blockDim.x + threadIdx.x;
    int slot = gid >> 5;
    int c4 = (gid & 31) << 2;
    int t = slot >> 7, m = slot & 127;
    int b = t / TPI, tt = t - b * TPI;
    int r, x0;
    decode_ctile(tt, r, x0);
    int xc = x0 + m;
    int rf = (256 - r) & 255, xf = (256 - xc) & 255;
    const float* xb = x + (size_t)b * 196608;
    int ip = r * 256 + xc, iq = rf * 256 + xf;
    float xp0 = __ldg(xb + ip), xp1 = __ldg(xb + ip + 65536), xp2 = __ldg(xb + ip + 131072);
    float xq0 = __ldg(xb + iq), xq1 = __ldg(xb + iq + 65536), xq2 = __ldg(xb + iq + 131072);
    float4 w0 = __ldg((const float4*)(w + c4));
    float4 w1 = __ldg((const float4*)(w + 128 + c4));
    float4 w2 = __ldg((const float4*)(w + 256 + c4));
    float4 bb = __ldg((const float4*)(bias + c4));
    float gp0 = gelu_exact(xp0 * w0.x + xp1 * w1.x + xp2 * w2.x + bb.x);
    float gp1 = gelu_exact(xp0 * w0.y + xp1 * w1.y + xp2 * w2.y + bb.y);
    float gp2 = gelu_exact(xp0 * w0.z + xp1 * w1.z + xp2 * w2.z + bb.z);
    float gp3 = gelu_exact(xp0 * w0.w + xp1 * w1.w + xp2 * w2.w + bb.w);
    float gf0 = gelu_exact(xq0 * w0.x + xq1 * w1.x + xq2 * w2.x + bb.x);
    float gf1 = gelu_exact(xq0 * w0.y + xq1 * w1.y + xq2 * w2.y + bb.y);
    float gf2 = gelu_exact(xq0 * w0.z + xq1 * w1.z + xq2 * w2.z + bb.z);
    float gf3 = gelu_exact(xq0 * w0.w + xq1 * w1.w + xq2 * w2.w + bb.w);
    float s0 = gp0 + gf0, s1 = gp1 + gf1, s2 = gp2 + gf2, s3 = gp3 + gf3;
    float d0 = gp0 - gf0, d1 = gp1 - gf1, d2 = gp2 - gf2, d3 = gp3 - gf3;

    int ht = slot >> 6, mm = slot & 63;
    uint32_t woff = (uint32_t)mm * 128u + ((((uint32_t)c4 & 63u) * 2u) ^ ((uint32_t)(mm & 7) << 4));
    char* base = (char*)act + (size_t)ht * 65536 + (size_t)(c4 >> 6) * 16384 + woff;
    uint2 v;
    v.x = pack_hi2(s0, s1); v.y = pack_hi2(s2, s3); *(uint2*)(base)         = v;
    v.x = pack_lo2(s0, s1); v.y = pack_lo2(s2, s3); *(uint2*)(base + 8192)  = v;
    v.x = pack_hi2(d0, d1); v.y = pack_hi2(d2, d3); *(uint2*)(base + 32768) = v;
    v.x = pack_lo2(d0, d1); v.y = pack_lo2(d2, d3); *(uint2*)(base + 40960) = v;
}

// ---------------------------------------------------------------------------
// Layer kernel: two 8-warp groups, A via cp.async.bulk + mbarrier
// ---------------------------------------------------------------------------
__global__ void __launch_bounds__(THREADS, 1) layer_kernel(
    const unsigned short* __restrict__ actIn,
    unsigned short* __restrict__ actOut,
    const uint4* __restrict__ wimgL,
    const float* __restrict__ cbp, const float* __restrict__ brp,
    const float* __restrict__ bip, const float* __restrict__ lowp,
    const float* __restrict__ lobp, float* __restrict__ gout, int fuse)
{
    extern __shared__ char dsm_raw[];
    __shared__ __align__(8) uint64_t s_mbar[6];
    uint32_t raw = smem_u32(dsm_raw);
    uint32_t sbase = (raw + 127) & ~127u;
    char* sm = dsm_raw + (sbase - raw);

    int tid = threadIdx.x, wid = tid >> 5, lane = tid & 31;
    int g = wid >> 3;
    int widg = wid & 7;
    int tidg = tid & 255;
    int wm = widg & 1;
    int wn = widg >> 1;
    uint32_t gsb = sbase + (uint32_t)g * 49152u;
    uint32_t mbB = smem_u32(&s_mbar[g * 3]);
    const char* actInB = (const char*)actIn;

    int start = blockIdx.x + g * GRID;
    int nloc = (NHT - start + 303) / 304;
    int totalC = nloc * 4;

    if (tid == 0) {
        uint32_t mb0 = smem_u32(&s_mbar[0]);
        #pragma unroll
        for (int j = 0; j < 6; j++) MBAR_INIT(mb0 + j * 8, 1);
    }
    __syncthreads();

    // prologue: elected thread issues chunks 0,1 into stages 0,1
    if (tidg == 0) {
        const char* src0 = actInB + (size_t)start * 65536;
        MBAR_EXPECT(mbB, 16384u);
        BULK_G2S(gsb, src0, mbB);
        MBAR_EXPECT(mbB + 8, 16384u);
        BULK_G2S(gsb + 16384u, src0 + 16384, mbB + 8);
    }
    // B image + biases
    {
        uint4* bs = (uint4*)(sm + SM_B);
        #pragma unroll
        for (int qq = 0; qq < 16; qq++)
            bs[tid + qq * 512] = __ldg(wimgL + tid + qq * 512);
        float* bf = (float*)(sm + SM_BIAS);
        if (tid < 128) {
            bf[tid]       = __ldg(cbp + tid);
            bf[128 + tid] = __ldg(brp + tid);
            bf[256 + tid] = __ldg(bip + tid);
            bf[384 + tid] = __ldg(lowp + tid);
        }
    }
    __syncthreads();
    if (g == 1) __nanosleep(1000);

    int grp = lane >> 3, lr = lane & 7;
    uint32_t xm = (uint32_t)(lr << 4);
    uint32_t a_c16 = (uint32_t)((grp >> 1) << 4);
    uint32_t b_c16 = (uint32_t)((grp & 1) << 4);
    uint32_t arow[2], brow[2];
    #pragma unroll
    for (int mt = 0; mt < 2; mt++)
        arow[mt] = (uint32_t)(wm * 32 + mt * 16 + lr + ((grp & 1) << 3)) * 128u;
    #pragma unroll
    for (int np = 0; np < 2; np++)
        brow[np] = (uint32_t)(wn * 32 + np * 16 + lr + ((grp >> 1) << 3)) * 128u;

    const float* cbS  = (const float*)(sm + SM_BIAS);
    const float* brS  = cbS + 128;
    const float* biS  = cbS + 256;
    const float* lowS = cbS + 384;

    uint32_t stM = 0, stI = 2, phz = 0;
    for (int i = 0; i < nloc; i++) {
        int ght = start + i * 304;
        int t = ght >> 1, half = ght & 1;
        int b = t / TPI, tt = t - b * TPI;
        int r, x0;
        decode_ctile(tt, r, x0);
        int x0h = x0 + half * 64;
        bool row0 = (r == 0);

        float accP[2][4][4], accQ[2][4][4];
        #pragma unroll
        for (int mt = 0; mt < 2; mt++)
            #pragma unroll
            for (int nt = 0; nt < 4; nt++)
                #pragma unroll
                for (int z = 0; z < 4; z++) { accP[mt][nt][z] = 0.0f; accQ[mt][nt][z] = 0.0f; }

        uint32_t stEpi = 0;
        #pragma unroll
        for (int cc = 0; cc < 4; cc++) {
            MBAR_WAIT(mbB + stM * 8, (phz >> stM) & 1u);
            phz ^= (1u << stM);
            GBAR(g);
            if (tidg == 0) {
                int gcc = i * 4 + cc + 2;
                if (gcc < totalC) {
                    int hti = start + (gcc >> 2) * 304;
                    const char* src = actInB + (size_t)hti * 65536 + (size_t)(gcc & 3) * 16384;
                    uint32_t mba = mbB + stI * 8;
                    MBAR_EXPECT(mba, 16384u);
                    BULK_G2S(gsb + stI * 16384u, src, mba);
                }
            }
            stI = (stI == 2) ? 0 : stI + 1;

            if (cc == 3) stEpi = stM;
            // banks: cc0 = As k0, cc1 = As k1, cc2 = Ad k0, cc3 = Ad k1
            uint32_t bOff = (cc < 2) ? ((uint32_t)cc * 16384u) : (65536u + (uint32_t)(cc - 2) * 16384u);
            if (cc < 2)
                mma_chunk(accP, gsb + stM * 16384u, sbase + SM_B + bOff, arow, brow, a_c16, b_c16, xm);
            else
                mma_chunk(accQ, gsb + stM * 16384u, sbase + SM_B + bOff, arow, brow, a_c16, b_c16, xm);
            stM = (stM == 2) ? 0 : stM + 1;
        }

        if (!fuse) {
            char* outB = (char*)actOut + (size_t)ght * 65536;
            #pragma unroll
            for (int mt = 0; mt < 2; mt++) {
                #pragma unroll
                for (int rh = 0; rh < 2; rh++) {
                    int mm = wm * 32 + mt * 16 + (lane >> 2) + rh * 8;
                    int xc = x0h + mm;
                    int xf = (256 - xc) & 255;
                    float sxp = row0 ? __ldg(&g_sx[xc]) : 0.0f;
                    float sxf = row0 ? __ldg(&g_sx[xf]) : 0.0f;
                    uint32_t swzm = (uint32_t)(mm & 7) << 4;
                    uint32_t rbase = (uint32_t)mm * 128u;
                    #pragma unroll
                    for (int nt = 0; nt < 4; nt++) {
                        int n = wn * 32 + nt * 8 + (lane & 3) * 2;
                        float P0 = accP[mt][nt][rh * 2], P1 = accP[mt][nt][rh * 2 + 1];
                        float Q0 = accQ[mt][nt][rh * 2], Q1 = accQ[mt][nt][rh * 2 + 1];
                        float c0 = cbS[n], c1 = cbS[n + 1];
                        float up0 = P0 + Q0 + c0, up1 = P1 + Q1 + c1;
                        float uf0 = P0 - Q0 + c0, uf1 = P1 - Q1 + c1;
                        if (row0) {
                            float b0 = biS[n], b1 = biS[n + 1];
                            up0 += b0 * sxp; up1 += b1 * sxp;
                            uf0 += b0 * sxf; uf1 += b1 * sxf;
                            if (xc == 0) {
                                up0 += brS[n]; up1 += brS[n + 1];
                                uf0 += brS[n]; uf1 += brS[n + 1];
                            }
                        }
                        float gp0 = gelu_exact(up0), gp1 = gelu_exact(up1);
                        float gf0 = gelu_exact(uf0), gf1 = gelu_exact(uf1);
                        float s0 = gp0 + gf0, s1 = gp1 + gf1;
                        float d0 = gp0 - gf0, d1 = gp1 - gf1;
                        uint32_t woff = rbase + ((((uint32_t)n & 63u) * 2u) ^ swzm);
                        char* pS = outB + (size_t)((n >> 6) * 16384) + woff;
                        *(uint32_t*)pS             = pack_hi2(s0, s1);
                        *(uint32_t*)(pS + 8192)    = pack_lo2(s0, s1);
                        *(uint32_t*)(pS + 32768)   = pack_hi2(d0, d1);
                        *(uint32_t*)(pS + 40960)   = pack_lo2(d0, d1);
                    }
                }
            }
        } else {
            float* red = (float*)(sm + (uint32_t)g * 49152u + stEpi * 16384u);
            float ppv[2][2], pfv[2][2];
            #pragma unroll
            for (int mt = 0; mt < 2; mt++) {
                #pragma unroll
                for (int rh = 0; rh < 2; rh++) {
                    int mm = wm * 32 + mt * 16 + (lane >> 2) + rh * 8;
                    int xc = x0h + mm;
                    int xf = (256 - xc) & 255;
                    float sxp = row0 ? __ldg(&g_sx[xc]) : 0.0f;
                    float sxf = row0 ? __ldg(&g_sx[xf]) : 0.0f;
                    float pp = 0.0f, pf = 0.0f;
                    #pragma unroll
                    for (int nt = 0; nt < 4; nt++) {
                        int n = wn * 32 + nt * 8 + (lane & 3) * 2;
                        float P0 = accP[mt][nt][rh * 2], P1 = accP[mt][nt][rh * 2 + 1];
                        float Q0 = accQ[mt][nt][rh * 2], Q1 = accQ[mt][nt][rh * 2 + 1];
                        float c0 = cbS[n], c1 = cbS[n + 1];
                        float up0 = P0 + Q0 + c0, up1 = P1 + Q1 + c1;
                        float uf0 = P0 - Q0 + c0, uf1 = P1 - Q1 + c1;
                        if (row0) {
                            float b0 = biS[n], b1 = biS[n + 1];
                            up0 += b0 * sxp; up1 += b1 * sxp;
                            uf0 += b0 * sxf; uf1 += b1 * sxf;
                            if (xc == 0) {
                                up0 += brS[n]; up1 += brS[n + 1];
                                uf0 += brS[n]; uf1 += brS[n + 1];
                            }
                        }
                        pp += gelu_exact(up0) * lowS[n] + gelu_exact(up1) * lowS[n + 1];
                        pf += gelu_exact(uf0) * lowS[n] + gelu_exact(uf1) * lowS[n + 1];
                    }
                    pp += __shfl_xor_sync(0xffffffffu, pp, 1);
                    pp += __shfl_xor_sync(0xffffffffu, pp, 2);
                    pf += __shfl_xor_sync(0xffffffffu, pf, 1);
                    pf += __shfl_xor_sync(0xffffffffu, pf, 2);
                    ppv[mt][rh] = pp; pfv[mt][rh] = pf;
                }
            }
            GBAR(g);
            if ((lane & 3) == 0) {
                #pragma unroll
                for (int mt = 0; mt < 2; mt++)
                    #pragma unroll
                    for (int rh = 0; rh < 2; rh++) {
                        int mm = wm * 32 + mt * 16 + (lane >> 2) + rh * 8;
                        red[wn * 64 + mm]       = ppv[mt][rh];
                        red[256 + wn * 64 + mm] = pfv[mt][rh];
                    }
            }
            GBAR(g);
            if (tidg < 64) {
                float lob = __ldg(lobp);
                float sp = red[tidg] + red[64 + tidg] + red[128 + tidg] + red[192 + tidg];
                float sf = red[256 + tidg] + red[320 + tidg] + red[384 + tidg] + red[448 + tidg];
                int xc = x0h + tidg, xf = (256 - xc) & 255, rf = (256 - r) & 255;
                gout[(size_t)b * 65536 + r * 256 + xc]  = gelu_exact(sp + lob);
                gout[(size_t)b * 65536 + rf * 256 + xf] = gelu_exact(sf + lob);
            }
            GBAR(g);   // red reads done before stage reuse
        }
    }
}

// ---------------------------------------------------------------------------
extern "C" void kernel_launch(void* const* d_in, const int* in_sizes, int n_in,
                              void* d_out, int out_size)
{
    const float* x   = (const float*)d_in[0];
    const float* liw = (const float*)d_in[1];
    const float* lib = (const float*)d_in[2];
    const float* wr  = (const float*)d_in[3];
    const float* wi  = (const float*)d_in[4];
    const float* br  = (const float*)d_in[5];
    const float* bi  = (const float*)d_in[6];
    const float* cw  = (const float*)d_in[7];
    const float* cb  = (const float*)d_in[8];
    const float* low = (const float*)d_in[9];
    const float* lob = (const float*)d_in[10];
    float* out = (float*)d_out;

    unsigned short *a0, *a1, *wimg;
    float* sx;
    cudaGetSymbolAddress((void**)&a0, g_act0);
    cudaGetSymbolAddress((void**)&a1, g_act1);
    cudaGetSymbolAddress((void**)&wimg, g_wimg);
    cudaGetSymbolAddress((void**)&sx, g_sx);

    cudaFuncSetAttribute(layer_kernel, cudaFuncAttributeMaxDynamicSharedMemorySize, SM_DYN);

    prep_w_kernel<<<512, 256>>>(wr, wi, cw, wimg);
    prep_sx_kernel<<<1, 256>>>(sx);
    in_kernel<<<NTILE_TOT * 128 * 32 / 256, 256>>>(x, liw, lib, a0);

    unsigned short* as[2] = { a0, a1 };
    for (int l = 0; l < NL; l++) {
        int fuse = (l == NL - 1) ? 1 : 0;
        layer_kernel<<<GRID, THREADS, SM_DYN>>>(
            as[l & 1], as[(l & 1) ^ 1],
            (const uint4*)(wimg + (size_t)l * 65536),
            cb + l * HID, br + l * HID, bi + l * HID,
            low, lob, out, fuse);
    }
}

// round 15
// speedup vs baseline: 1.2603x; 1.0041x over previous
#include <cuda_runtime.h>
#include <cuda_bf16.h>
#include <math.h>
#include <stdint.h>

#define HID 128
#define NL 4
#define TPI 258
#define NTILE_TOT (TPI*4)          // 1032 canonical tiles
#define NHT (NTILE_TOT*2)          // 2064 half-tiles (64 pixels each)
#define GRID 152
#define THREADS 512
#define PART 16908288

// Activation buffer: pre-swizzled 64KB images per half-tile:
// [ht][bank: s-k0 | s-k1 | d-k0 | d-k1], bank = [hi 8KB | lo 8KB], 64 rows x 128B
__device__ unsigned short g_act0[4*(size_t)PART];
__device__ unsigned short g_wimg[NL * 65536];
__device__ float g_sx[256];

__device__ __forceinline__ uint32_t smem_u32(const void* p) {
    uint32_t a;
    asm("{ .reg .u64 t; cvta.to.shared.u64 t, %1; cvt.u32.u64 %0, t; }" : "=r"(a) : "l"(p));
    return a;
}
__device__ __forceinline__ void ldsm4(uint32_t& r0, uint32_t& r1, uint32_t& r2, uint32_t& r3, uint32_t addr) {
    asm volatile("ldmatrix.sync.aligned.m8n8.x4.shared.b16 {%0,%1,%2,%3}, [%4];"
        : "=r"(r0), "=r"(r1), "=r"(r2), "=r"(r3) : "r"(addr));
}
__device__ __forceinline__ void mma16816(float* d, const uint32_t* a, uint32_t b0, uint32_t b1) {
    asm volatile("mma.sync.aligned.m16n8k16.row.col.f32.bf16.bf16.f32 "
        "{%0,%1,%2,%3}, {%4,%5,%6,%7}, {%8,%9}, {%0,%1,%2,%3};"
        : "+f"(d[0]), "+f"(d[1]), "+f"(d[2]), "+f"(d[3])
        : "r"(a[0]), "r"(a[1]), "r"(a[2]), "r"(a[3]), "r"(b0), "r"(b1));
}
#define MBAR_INIT(a, c) asm volatile("mbarrier.init.shared.b64 [%0], %1;" :: "r"(a), "r"(c) : "memory")
#define MBAR_EXPECT(a, b) asm volatile("mbarrier.arrive.expect_tx.shared.b64 _, [%0], %1;" :: "r"(a), "r"(b) : "memory")
#define BULK_G2S(dst, src, bytes, mb) asm volatile( \
    "cp.async.bulk.shared::cluster.global.mbarrier::complete_tx::bytes [%0], [%1], %2, [%3];" \
    :: "r"(dst), "l"(src), "r"(bytes), "r"(mb) : "memory")
#define MBAR_WAIT(addr, par) do { \
    asm volatile("{\n\t.reg .pred P;\n\tWAITL_%=:\n\t" \
        "mbarrier.try_wait.parity.shared.b64 P, [%0], %1;\n\t" \
        "@P bra.uni WAITD_%=;\n\tbra.uni WAITL_%=;\n\tWAITD_%=:\n\t}" \
        :: "r"(addr), "r"(par) : "memory"); \
} while(0)

__device__ __forceinline__ float gelu_exact(float v) {
    return 0.5f * v * (1.0f + erff(v * 0.70710678118654752f));
}
__device__ __forceinline__ uint32_t pack_hi2(float a, float b) {
    return __byte_perm(__float_as_uint(a), __float_as_uint(b), 0x7632);
}
__device__ __forceinline__ uint32_t pack_lo2(float a, float b) {
    float ra = a - __uint_as_float(__float_as_uint(a) & 0xffff0000u);
    float rb = b - __uint_as_float(__float_as_uint(b) & 0xffff0000u);
    __nv_bfloat162 p = __floats2bfloat162_rn(ra, rb);
    return *reinterpret_cast<uint32_t*>(&p);
}
__device__ __forceinline__ void decode_ctile(int tt, int& r, int& x0) {
    if (tt < 254)      { r = 1 + (tt >> 1); x0 = (tt & 1) << 7; }
    else if (tt < 256) { r = 0;             x0 = (tt - 254) << 7; }
    else               { r = 128;           x0 = (tt - 256) << 7; }
}

// One GEMM bank over K=128 (two 16KB k-chunks), warp tile m16 x n32, 3-combo
__device__ __forceinline__ void mma_bank(
    float (&acc)[4][4], uint32_t aBank, uint32_t bBank,
    uint32_t arowb, const uint32_t (&brow)[2],
    uint32_t a_c16, uint32_t b_c16, uint32_t xm)
{
    #pragma unroll
    for (int kc = 0; kc < 2; kc++) {
        uint32_t aB = aBank + (uint32_t)kc * 16384u;
        uint32_t bB = bBank + (uint32_t)kc * 16384u;
        #pragma unroll
        for (int ks = 0; ks < 4; ks++) {
            uint32_t acb = ((uint32_t)(ks * 32) + a_c16) ^ xm;
            uint32_t bcb = ((uint32_t)(ks * 32) + b_c16) ^ xm;
            uint32_t af[4], bh[2][4], bl[2][4];
            ldsm4(af[0], af[1], af[2], af[3], aB + arowb + acb);
            #pragma unroll
            for (int np = 0; np < 2; np++) {
                ldsm4(bh[np][0], bh[np][1], bh[np][2], bh[np][3], bB + brow[np] + bcb);
                ldsm4(bl[np][0], bl[np][1], bl[np][2], bl[np][3], bB + 32768u + brow[np] + bcb);
            }
            #pragma unroll
            for (int np = 0; np < 2; np++) {
                mma16816(acc[np * 2],     af, bh[np][0], bh[np][1]);
                mma16816(acc[np * 2 + 1], af, bh[np][2], bh[np][3]);
            }
            #pragma unroll
            for (int np = 0; np < 2; np++) {
                mma16816(acc[np * 2],     af, bl[np][0], bl[np][1]);
                mma16816(acc[np * 2 + 1], af, bl[np][2], bl[np][3]);
            }
            ldsm4(af[0], af[1], af[2], af[3], aB + 8192u + arowb + acb);
            #pragma unroll
            for (int np = 0; np < 2; np++) {
                mma16816(acc[np * 2],     af, bh[np][0], bh[np][1]);
                mma16816(acc[np * 2 + 1], af, bh[np][2], bh[np][3]);
            }
        }
    }
}

// SMEM: A 64KB @0 | B buf0 64KB @65536 | B buf1 64KB @131072 | bias 8KB | red 4KB
#define SM_B0   65536u
#define SM_B1   131072u
#define SM_BIAS 196608u
#define SM_RED  204800u
#define SM_DYN  208896

// ---------------------------------------------------------------------------
__global__ void prep_w_kernel(const float* __restrict__ wr,
                              const float* __restrict__ wi,
                              const float* __restrict__ cw,
                              unsigned short* __restrict__ wimg)
{
    int idx = blockIdx.x * blockDim.x + threadIdx.x;   // < 131072
    int l = idx >> 15;
    int rem = idx & 32767;
    int sel = rem >> 14;
    int rem2 = rem & 16383;
    int kc2 = rem2 >> 13;
    int rem3 = rem2 & 8191;
    int o = rem3 >> 6;
    int kl = rem3 & 63;
    int k = kc2 * 64 + kl;
    const float* wsel = (sel ? wi : wr) + (size_t)l * 16384;
    float v = 0.5f * (cw[(size_t)l * 16384 + o * 128 + k] + wsel[k * 128 + o]);
    uint32_t u = __float_as_uint(v);
    float hf = __uint_as_float(u & 0xffff0000u);
    float lo = v - hf;
    uint32_t off = (uint32_t)o * 128 + kl * 2;
    off ^= (off >> 3) & 0x70;
    size_t base = (size_t)l * 65536 + sel * 32768 + kc2 * 8192;
    wimg[base + (off >> 1)] = (unsigned short)(u >> 16);
    __nv_bfloat16 lb = __float2bfloat16_rn(lo);
    wimg[base + 16384 + (off >> 1)] = __bfloat16_as_ushort(lb);
}

__global__ void prep_sx_kernel(float* __restrict__ sx)
{
    int x = threadIdx.x;
    double s = 0.0;
    if (x) {
        double th = M_PI * (double)x / 128.0;
        s = sin(63.5 * th) * sin(64.0 * th) / sin(0.5 * th);
    }
    sx[x] = (float)(-s / 128.0);
}

// ---------------------------------------------------------------------------
// Input transform -> pre-swizzled s/d bank images (64KB per half-tile)
// ---------------------------------------------------------------------------
__global__ void in_kernel(const float* __restrict__ x,
                          const float* __restrict__ w,
                          const float* __restrict__ bias,
                          unsigned short* __restrict__ act)
{
    int gid = blockIdx.x * blockDim.x + threadIdx.x;
    int slot = gid >> 5;
    int c4 = (gid & 31) << 2;
    int t = slot >> 7, m = slot & 127;
    int b = t / TPI, tt = t - b * TPI;
    int r, x0;
    decode_ctile(tt, r, x0);
    int xc = x0 + m;
    int rf = (256 - r) & 255, xf = (256 - xc) & 255;
    const float* xb = x + (size_t)b * 196608;
    int ip = r * 256 + xc, iq = rf * 256 + xf;
    float xp0 = __ldg(xb + ip), xp1 = __ldg(xb + ip + 65536), xp2 = __ldg(xb + ip + 131072);
    float xq0 = __ldg(xb + iq), xq1 = __ldg(xb + iq + 65536), xq2 = __ldg(xb + iq + 131072);
    float4 w0 = __ldg((const float4*)(w + c4));
    float4 w1 = __ldg((const float4*)(w + 128 + c4));
    float4 w2 = __ldg((const float4*)(w + 256 + c4));
    float4 bb = __ldg((const float4*)(bias + c4));
    float gp0 = gelu_exact(xp0 * w0.x + xp1 * w1.x + xp2 * w2.x + bb.x);
    float gp1 = gelu_exact(xp0 * w0.y + xp1 * w1.y + xp2 * w2.y + bb.y);
    float gp2 = gelu_exact(xp0 * w0.z + xp1 * w1.z + xp2 * w2.z + bb.z);
    float gp3 = gelu_exact(xp0 * w0.w + xp1 * w1.w + xp2 * w2.w + bb.w);
    float gf0 = gelu_exact(xq0 * w0.x + xq1 * w1.x + xq2 * w2.x + bb.x);
    float gf1 = gelu_exact(xq0 * w0.y + xq1 * w1.y + xq2 * w2.y + bb.y);
    float gf2 = gelu_exact(xq0 * w0.z + xq1 * w1.z + xq2 * w2.z + bb.z);
    float gf3 = gelu_exact(xq0 * w0.w + xq1 * w1.w + xq2 * w2.w + bb.w);
    float s0 = gp0 + gf0, s1 = gp1 + gf1, s2 = gp2 + gf2, s3 = gp3 + gf3;
    float d0 = gp0 - gf0, d1 = gp1 - gf1, d2 = gp2 - gf2, d3 = gp3 - gf3;

    int ht = slot >> 6, mm = slot & 63;
    uint32_t woff = (uint32_t)mm * 128u + ((((uint32_t)c4 & 63u) * 2u) ^ ((uint32_t)(mm & 7) << 4));
    char* base = (char*)act + (size_t)ht * 65536 + (size_t)(c4 >> 6) * 16384 + woff;
    uint2 v;
    v.x = pack_hi2(s0, s1); v.y = pack_hi2(s2, s3); *(uint2*)(base)         = v;
    v.x = pack_lo2(s0, s1); v.y = pack_lo2(s2, s3); *(uint2*)(base + 8192)  = v;
    v.x = pack_hi2(d0, d1); v.y = pack_hi2(d2, d3); *(uint2*)(base + 32768) = v;
    v.x = pack_lo2(d0, d1); v.y = pack_lo2(d2, d3); *(uint2*)(base + 40960) = v;
}

// ---------------------------------------------------------------------------
// Fused 4-layer kernel: tile-resident s/d, per-layer B streamed from L2
// ---------------------------------------------------------------------------
__global__ void __launch_bounds__(THREADS, 1) fused_kernel(
    const unsigned short* __restrict__ actIn,
    const char* __restrict__ wimgB,
    const float* __restrict__ cbp, const float* __restrict__ brp,
    const float* __restrict__ bip, const float* __restrict__ lowp,
    const float* __restrict__ lobp, float* __restrict__ gout)
{
    extern __shared__ char dsm_raw[];
    __shared__ __align__(8) uint64_t s_mbar[3];
    uint32_t raw = smem_u32(dsm_raw);
    uint32_t sbase = (raw + 127) & ~127u;
    char* sm = dsm_raw + (sbase - raw);

    int tid = threadIdx.x, wid = tid >> 5, lane = tid & 31;
    int g = wid & 3;          // n-group: n in [32g, 32g+32)
    int widg = wid >> 2;      // m-slice: rows [16*widg, +16)

    uint32_t mbA  = smem_u32(&s_mbar[0]);
    uint32_t mbB0 = smem_u32(&s_mbar[1]);
    uint32_t mbB1 = smem_u32(&s_mbar[2]);

    int nloc = (NHT - blockIdx.x + GRID - 1) / GRID;

    if (tid == 0) {
        MBAR_INIT(mbA, 1); MBAR_INIT(mbB0, 1); MBAR_INIT(mbB1, 1);
        // prologue loads: A tile 0, As_0, Ad_0
        MBAR_EXPECT(mbA, 65536u);
        BULK_G2S(sbase, (const char*)actIn + (size_t)blockIdx.x * 65536, 65536u, mbA);
        MBAR_EXPECT(mbB0, 65536u);
        BULK_G2S(sbase + SM_B0, wimgB, 65536u, mbB0);
        MBAR_EXPECT(mbB1, 65536u);
        BULK_G2S(sbase + SM_B1, wimgB + 65536, 65536u, mbB1);
    }
    // biases for all 4 layers + low
    {
        float* bf = (float*)(sm + SM_BIAS);
        bf[tid]        = __ldg(cbp + tid);    // 512 = 4x128
        bf[512 + tid]  = __ldg(brp + tid);
        bf[1024 + tid] = __ldg(bip + tid);
        if (tid < 128) bf[1536 + tid] = __ldg(lowp + tid);
    }
    __syncthreads();

    // ldsm lane constants
    int grp = lane >> 3, lr = lane & 7;
    uint32_t xm = (uint32_t)(lr << 4);
    uint32_t a_c16 = (uint32_t)((grp >> 1) << 4);
    uint32_t b_c16 = (uint32_t)((grp & 1) << 4);
    uint32_t arowb = (uint32_t)(widg * 16 + lr + ((grp & 1) << 3)) * 128u;
    uint32_t brow[2];
    #pragma unroll
    for (int np = 0; np < 2; np++)
        brow[np] = (uint32_t)(g * 32 + np * 16 + lr + ((grp >> 1) << 3)) * 128u;

    float* red = (float*)(sm + SM_RED);
    int na = 0, nb0 = 0, nb1 = 0;

    for (int i = 0; i < nloc; i++) {
        int ht = blockIdx.x + i * GRID;
        int t = ht >> 1, hx = ht & 1;
        int b = t / TPI, tt = t - b * TPI;
        int r, x0;
        decode_ctile(tt, r, x0);
        int x0h = x0 + hx * 64;
        bool row0 = (r == 0);
        bool haveNext = (i + 1 < nloc);

        MBAR_WAIT(mbA, na & 1); na++;

        #pragma unroll 1
        for (int l = 0; l < 4; l++) {
            float accP[4][4], accQ[4][4];
            #pragma unroll
            for (int nt = 0; nt < 4; nt++)
                #pragma unroll
                for (int z = 0; z < 4; z++) { accP[nt][z] = 0.0f; accQ[nt][z] = 0.0f; }

            MBAR_WAIT(mbB0, nb0 & 1); nb0++;
            mma_bank(accP, sbase, sbase + SM_B0, arowb, brow, a_c16, b_c16, xm);
            MBAR_WAIT(mbB1, nb1 & 1); nb1++;
            mma_bank(accQ, sbase + 32768u, sbase + SM_B1, arowb, brow, a_c16, b_c16, xm);
            __syncthreads();   // all A/B reads of this layer complete

            if (tid == 0) {
                if (l < 3) {
                    MBAR_EXPECT(mbB0, 65536u);
                    BULK_G2S(sbase + SM_B0, wimgB + (size_t)(l + 1) * 131072, 65536u, mbB0);
                    MBAR_EXPECT(mbB1, 65536u);
                    BULK_G2S(sbase + SM_B1, wimgB + (size_t)(l + 1) * 131072 + 65536, 65536u, mbB1);
                } else if (haveNext) {
                    MBAR_EXPECT(mbA, 65536u);
                    BULK_G2S(sbase, (const char*)actIn + (size_t)(ht + GRID) * 65536, 65536u, mbA);
                    MBAR_EXPECT(mbB0, 65536u);
                    BULK_G2S(sbase + SM_B0, wimgB, 65536u, mbB0);
                    MBAR_EXPECT(mbB1, 65536u);
                    BULK_G2S(sbase + SM_B1, wimgB + 65536, 65536u, mbB1);
                }
            }

            const float* cbS = (const float*)(sm + SM_BIAS) + l * 128;
            const float* brS = (const float*)(sm + SM_BIAS) + 512 + l * 128;
            const float* biS = (const float*)(sm + SM_BIAS) + 1024 + l * 128;

            if (l < 3) {
                // in-place epilogue: write s'/d' back into A banks
                #pragma unroll
                for (int rh = 0; rh < 2; rh++) {
                    int p = widg * 16 + (lane >> 2) + rh * 8;
                    int xc = x0h + p;
                    int xf = (256 - xc) & 255;
                    float sxp = row0 ? __ldg(&g_sx[xc]) : 0.0f;
                    float sxf = row0 ? __ldg(&g_sx[xf]) : 0.0f;
                    uint32_t rowoff = (uint32_t)p * 128u;
                    uint32_t swz = (uint32_t)(p & 7) << 4;
                    #pragma unroll
                    for (int nt = 0; nt < 4; nt++) {
                        int n = g * 32 + nt * 8 + (lane & 3) * 2;
                        float P0 = accP[nt][rh * 2], P1 = accP[nt][rh * 2 + 1];
                        float Q0 = accQ[nt][rh * 2], Q1 = accQ[nt][rh * 2 + 1];
                        float c0 = cbS[n], c1 = cbS[n + 1];
                        float up0 = P0 + Q0 + c0, up1 = P1 + Q1 + c1;
                        float uf0 = P0 - Q0 + c0, uf1 = P1 - Q1 + c1;
                        if (row0) {
                            float b0 = biS[n], b1 = biS[n + 1];
                            up0 += b0 * sxp; up1 += b1 * sxp;
                            uf0 += b0 * sxf; uf1 += b1 * sxf;
                            if (xc == 0) {
                                up0 += brS[n]; up1 += brS[n + 1];
                                uf0 += brS[n]; uf1 += brS[n + 1];
                            }
                        }
                        float gp0 = gelu_exact(up0), gp1 = gelu_exact(up1);
                        float gf0 = gelu_exact(uf0), gf1 = gelu_exact(uf1);
                        float s0 = gp0 + gf0, s1 = gp1 + gf1;
                        float d0 = gp0 - gf0, d1 = gp1 - gf1;
                        uint32_t off = (uint32_t)(n >> 6) * 16384u + rowoff
                                     + ((((uint32_t)n & 63u) * 2u) ^ swz);
                        *(uint32_t*)(sm + off)          = pack_hi2(s0, s1);
                        *(uint32_t*)(sm + off + 8192u)  = pack_lo2(s0, s1);
                        *(uint32_t*)(sm + off + 32768u) = pack_hi2(d0, d1);
                        *(uint32_t*)(sm + off + 40960u) = pack_lo2(d0, d1);
                    }
                }
                __syncthreads();   // writes visible before next layer's MMA
            } else {
                // final fused output: out = gelu( sum_n gelu(u_n)*low[n] + lob )
                const float* lowS = (const float*)(sm + SM_BIAS) + 1536;
                #pragma unroll
                for (int rh = 0; rh < 2; rh++) {
                    int p = widg * 16 + (lane >> 2) + rh * 8;
                    int xc = x0h + p;
                    int xf = (256 - xc) & 255;
                    float sxp = row0 ? __ldg(&g_sx[xc]) : 0.0f;
                    float sxf = row0 ? __ldg(&g_sx[xf]) : 0.0f;
                    float pp = 0.0f, pf = 0.0f;
                    #pragma unroll
                    for (int nt = 0; nt < 4; nt++) {
                        int n = g * 32 + nt * 8 + (lane & 3) * 2;
                        float P0 = accP[nt][rh * 2], P1 = accP[nt][rh * 2 + 1];
                        float Q0 = accQ[nt][rh * 2], Q1 = accQ[nt][rh * 2 + 1];
                        float c0 = cbS[n], c1 = cbS[n + 1];
                        float up0 = P0 + Q0 + c0, up1 = P1 + Q1 + c1;
                        float uf0 = P0 - Q0 + c0, uf1 = P1 - Q1 + c1;
                        if (row0) {
                            float b0 = biS[n], b1 = biS[n + 1];
                            up0 += b0 * sxp; up1 += b1 * sxp;
                            uf0 += b0 * sxf; uf1 += b1 * sxf;
                            if (xc == 0) {
                                up0 += brS[n]; up1 += brS[n + 1];
                                uf0 += brS[n]; uf1 += brS[n + 1];
                            }
                        }
                        pp += gelu_exact(up0) * lowS[n] + gelu_exact(up1) * lowS[n + 1];
                        pf += gelu_exact(uf0) * lowS[n] + gelu_exact(uf1) * lowS[n + 1];
                    }
                    pp += __shfl_xor_sync(0xffffffffu, pp, 1);
                    pp += __shfl_xor_sync(0xffffffffu, pp, 2);
                    pf += __shfl_xor_sync(0xffffffffu, pf, 1);
                    pf += __shfl_xor_sync(0xffffffffu, pf, 2);
                    if ((lane & 3) == 0) {
                        red[g * 128 + p] = pp;
                        red[512 + g * 128 + p] = pf;
                    }
                }
                __syncthreads();
                if (tid < 64) {
                    float lob = __ldg(lobp);
                    float sp = red[tid] + red[128 + tid] + red[256 + tid] + red[384 + tid];
                    float sf = red[512 + tid] + red[640 + tid] + red[768 + tid] + red[896 + tid];
                    int xc = x0h + tid, xf = (256 - xc) & 255, rf = (256 - r) & 255;
                    gout[(size_t)b * 65536 + r * 256 + xc]  = gelu_exact(sp + __ldg(lobp) * 0.0f + lob);
                    gout[(size_t)b * 65536 + rf * 256 + xf] = gelu_exact(sf + lob);
                }
                __syncthreads();
            }
        }
    }
}

// ---------------------------------------------------------------------------
extern "C" void kernel_launch(void* const* d_in, const int* in_sizes, int n_in,
                              void* d_out, int out_size)
{
    const float* x   = (const float*)d_in[0];
    const float* liw = (const float*)d_in[1];
    const float* lib = (const float*)d_in[2];
    const float* wr  = (const float*)d_in[3];
    const float* wi  = (const float*)d_in[4];
    const float* br  = (const float*)d_in[5];
    const float* bi  = (const float*)d_in[6];
    const float* cw  = (const float*)d_in[7];
    const float* cb  = (const float*)d_in[8];
    const float* low = (const float*)d_in[9];
    const float* lob = (const float*)d_in[10];
    float* out = (float*)d_out;

    unsigned short *a0, *wimg;
    float* sx;
    cudaGetSymbolAddress((void**)&a0, g_act0);
    cudaGetSymbolAddress((void**)&wimg, g_wimg);
    cudaGetSymbolAddress((void**)&sx, g_sx);

    cudaFuncSetAttribute(fused_kernel, cudaFuncAttributeMaxDynamicSharedMemorySize, SM_DYN);

    prep_w_kernel<<<512, 256>>>(wr, wi, cw, wimg);
    prep_sx_kernel<<<1, 256>>>(sx);
    in_kernel<<<NTILE_TOT * 128 * 32 / 256, 256>>>(x, liw, lib, a0);

    fused_kernel<<<GRID, THREADS, SM_DYN>>>(
        a0, (const char*)wimg, cb, br, bi, low, lob, out);
}

// round 16
// speedup vs baseline: 1.3176x; 1.0455x over previous
#include <cuda_runtime.h>
#include <cuda_bf16.h>
#include <math.h>
#include <stdint.h>

#define HID 128
#define NL 4
#define TPI 258
#define NTILE_TOT (TPI*4)          // 1032 canonical tiles
#define NHT (NTILE_TOT*2)          // 2064 half-tiles (64 pixels each)
#define GRID 152
#define THREADS 512
#define PART 16908288

// Activation buffer: pre-swizzled 64KB images per half-tile:
// [ht][bank: s-k0 | s-k1 | d-k0 | d-k1], bank = [hi 8KB | lo 8KB], 64 rows x 128B
__device__ unsigned short g_act0[4*(size_t)PART];
__device__ unsigned short g_wimg[NL * 65536];
__device__ float g_sx[256];

__device__ __forceinline__ uint32_t smem_u32(const void* p) {
    uint32_t a;
    asm("{ .reg .u64 t; cvta.to.shared.u64 t, %1; cvt.u32.u64 %0, t; }" : "=r"(a) : "l"(p));
    return a;
}
__device__ __forceinline__ void ldsm4(uint32_t& r0, uint32_t& r1, uint32_t& r2, uint32_t& r3, uint32_t addr) {
    asm volatile("ldmatrix.sync.aligned.m8n8.x4.shared.b16 {%0,%1,%2,%3}, [%4];"
        : "=r"(r0), "=r"(r1), "=r"(r2), "=r"(r3) : "r"(addr));
}
__device__ __forceinline__ void mma16816(float* d, const uint32_t* a, uint32_t b0, uint32_t b1) {
    asm volatile("mma.sync.aligned.m16n8k16.row.col.f32.bf16.bf16.f32 "
        "{%0,%1,%2,%3}, {%4,%5,%6,%7}, {%8,%9}, {%0,%1,%2,%3};"
        : "+f"(d[0]), "+f"(d[1]), "+f"(d[2]), "+f"(d[3])
        : "r"(a[0]), "r"(a[1]), "r"(a[2]), "r"(a[3]), "r"(b0), "r"(b1));
}
#define GBAR(gid) asm volatile("bar.sync %0, 256;" :: "r"((gid) + 1) : "memory")
#define MBAR_INIT(a, c) asm volatile("mbarrier.init.shared.b64 [%0], %1;" :: "r"(a), "r"(c) : "memory")
#define MBAR_EXPECT(a, b) asm volatile("mbarrier.arrive.expect_tx.shared.b64 _, [%0], %1;" :: "r"(a), "r"(b) : "memory")
#define BULK_G2S(dst, src, bytes, mb) asm volatile( \
    "cp.async.bulk.shared::cluster.global.mbarrier::complete_tx::bytes [%0], [%1], %2, [%3];" \
    :: "r"(dst), "l"(src), "r"(bytes), "r"(mb) : "memory")
#define MBAR_WAIT(addr, par) do { \
    asm volatile("{\n\t.reg .pred P;\n\tWAITL_%=:\n\t" \
        "mbarrier.try_wait.parity.shared.b64 P, [%0], %1;\n\t" \
        "@P bra.uni WAITD_%=;\n\tbra.uni WAITL_%=;\n\tWAITD_%=:\n\t}" \
        :: "r"(addr), "r"(par) : "memory"); \
} while(0)

__device__ __forceinline__ float gelu_exact(float v) {
    return 0.5f * v * (1.0f + erff(v * 0.70710678118654752f));
}
__device__ __forceinline__ uint32_t pack_hi2(float a, float b) {
    return __byte_perm(__float_as_uint(a), __float_as_uint(b), 0x7632);
}
__device__ __forceinline__ uint32_t pack_lo2(float a, float b) {
    float ra = a - __uint_as_float(__float_as_uint(a) & 0xffff0000u);
    float rb = b - __uint_as_float(__float_as_uint(b) & 0xffff0000u);
    __nv_bfloat162 p = __floats2bfloat162_rn(ra, rb);
    return *reinterpret_cast<uint32_t*>(&p);
}
__device__ __forceinline__ void decode_ctile(int tt, int& r, int& x0) {
    if (tt < 254)      { r = 1 + (tt >> 1); x0 = (tt & 1) << 7; }
    else if (tt < 256) { r = 0;             x0 = (tt - 254) << 7; }
    else               { r = 128;           x0 = (tt - 256) << 7; }
}

// One GEMM bank over K=128, warp tile m16 x n32, 3-combo bf16 split
__device__ __forceinline__ void mma_bank(
    float (&acc)[4][4], uint32_t aBank, uint32_t bBank,
    uint32_t arowb, const uint32_t (&brow)[2],
    uint32_t a_c16, uint32_t b_c16, uint32_t xm)
{
    #pragma unroll
    for (int kc = 0; kc < 2; kc++) {
        uint32_t aB = aBank + (uint32_t)kc * 16384u;
        uint32_t bB = bBank + (uint32_t)kc * 16384u;
        #pragma unroll
        for (int ks = 0; ks < 4; ks++) {
            uint32_t acb = ((uint32_t)(ks * 32) + a_c16) ^ xm;
            uint32_t bcb = ((uint32_t)(ks * 32) + b_c16) ^ xm;
            uint32_t af[4], bh[2][4], bl[2][4];
            ldsm4(af[0], af[1], af[2], af[3], aB + arowb + acb);
            #pragma unroll
            for (int np = 0; np < 2; np++) {
                ldsm4(bh[np][0], bh[np][1], bh[np][2], bh[np][3], bB + brow[np] + bcb);
                ldsm4(bl[np][0], bl[np][1], bl[np][2], bl[np][3], bB + 32768u + brow[np] + bcb);
            }
            #pragma unroll
            for (int np = 0; np < 2; np++) {
                mma16816(acc[np * 2],     af, bh[np][0], bh[np][1]);
                mma16816(acc[np * 2 + 1], af, bh[np][2], bh[np][3]);
            }
            #pragma unroll
            for (int np = 0; np < 2; np++) {
                mma16816(acc[np * 2],     af, bl[np][0], bl[np][1]);
                mma16816(acc[np * 2 + 1], af, bl[np][2], bl[np][3]);
            }
            ldsm4(af[0], af[1], af[2], af[3], aB + 8192u + arowb + acb);
            #pragma unroll
            for (int np = 0; np < 2; np++) {
                mma16816(acc[np * 2],     af, bh[np][0], bh[np][1]);
                mma16816(acc[np * 2 + 1], af, bh[np][2], bh[np][3]);
            }
        }
    }
}

// SMEM: A 64KB @0 | B0 64KB @65536 | B1 64KB @131072 | bias 8KB | red 2x1KB
#define SM_B0   65536u
#define SM_B1   131072u
#define SM_BIAS 196608u
#define SM_RED  204800u
#define SM_DYN  208896

// ---------------------------------------------------------------------------
__global__ void prep_w_kernel(const float* __restrict__ wr,
                              const float* __restrict__ wi,
                              const float* __restrict__ cw,
                              unsigned short* __restrict__ wimg)
{
    int idx = blockIdx.x * blockDim.x + threadIdx.x;   // < 131072
    int l = idx >> 15;
    int rem = idx & 32767;
    int sel = rem >> 14;
    int rem2 = rem & 16383;
    int kc2 = rem2 >> 13;
    int rem3 = rem2 & 8191;
    int o = rem3 >> 6;
    int kl = rem3 & 63;
    int k = kc2 * 64 + kl;
    const float* wsel = (sel ? wi : wr) + (size_t)l * 16384;
    float v = 0.5f * (cw[(size_t)l * 16384 + o * 128 + k] + wsel[k * 128 + o]);
    uint32_t u = __float_as_uint(v);
    float hf = __uint_as_float(u & 0xffff0000u);
    float lo = v - hf;
    uint32_t off = (uint32_t)o * 128 + kl * 2;
    off ^= (off >> 3) & 0x70;
    size_t base = (size_t)l * 65536 + sel * 32768 + kc2 * 8192;
    wimg[base + (off >> 1)] = (unsigned short)(u >> 16);
    __nv_bfloat16 lb = __float2bfloat16_rn(lo);
    wimg[base + 16384 + (off >> 1)] = __bfloat16_as_ushort(lb);
}

__global__ void prep_sx_kernel(float* __restrict__ sx)
{
    int x = threadIdx.x;
    double s = 0.0;
    if (x) {
        double th = M_PI * (double)x / 128.0;
        s = sin(63.5 * th) * sin(64.0 * th) / sin(0.5 * th);
    }
    sx[x] = (float)(-s / 128.0);
}

// ---------------------------------------------------------------------------
// Input transform -> pre-swizzled s/d bank images (64KB per half-tile)
// ---------------------------------------------------------------------------
__global__ void in_kernel(const float* __restrict__ x,
                          const float* __restrict__ w,
                          const float* __restrict__ bias,
                          unsigned short* __restrict__ act)
{
    int gid = blockIdx.x * blockDim.x + threadIdx.x;
    int slot = gid >> 5;
    int c4 = (gid & 31) << 2;
    int t = slot >> 7, m = slot & 127;
    int b = t / TPI, tt = t - b * TPI;
    int r, x0;
    decode_ctile(tt, r, x0);
    int xc = x0 + m;
    int rf = (256 - r) & 255, xf = (256 - xc) & 255;
    const float* xb = x + (size_t)b * 196608;
    int ip = r * 256 + xc, iq = rf * 256 + xf;
    float xp0 = __ldg(xb + ip), xp1 = __ldg(xb + ip + 65536), xp2 = __ldg(xb + ip + 131072);
    float xq0 = __ldg(xb + iq), xq1 = __ldg(xb + iq + 65536), xq2 = __ldg(xb + iq + 131072);
    float4 w0 = __ldg((const float4*)(w + c4));
    float4 w1 = __ldg((const float4*)(w + 128 + c4));
    float4 w2 = __ldg((const float4*)(w + 256 + c4));
    float4 bb = __ldg((const float4*)(bias + c4));
    float gp0 = gelu_exact(xp0 * w0.x + xp1 * w1.x + xp2 * w2.x + bb.x);
    float gp1 = gelu_exact(xp0 * w0.y + xp1 * w1.y + xp2 * w2.y + bb.y);
    float gp2 = gelu_exact(xp0 * w0.z + xp1 * w1.z + xp2 * w2.z + bb.z);
    float gp3 = gelu_exact(xp0 * w0.w + xp1 * w1.w + xp2 * w2.w + bb.w);
    float gf0 = gelu_exact(xq0 * w0.x + xq1 * w1.x + xq2 * w2.x + bb.x);
    float gf1 = gelu_exact(xq0 * w0.y + xq1 * w1.y + xq2 * w2.y + bb.y);
    float gf2 = gelu_exact(xq0 * w0.z + xq1 * w1.z + xq2 * w2.z + bb.z);
    float gf3 = gelu_exact(xq0 * w0.w + xq1 * w1.w + xq2 * w2.w + bb.w);
    float s0 = gp0 + gf0, s1 = gp1 + gf1, s2 = gp2 + gf2, s3 = gp3 + gf3;
    float d0 = gp0 - gf0, d1 = gp1 - gf1, d2 = gp2 - gf2, d3 = gp3 - gf3;

    int ht = slot >> 6, mm = slot & 63;
    uint32_t woff = (uint32_t)mm * 128u + ((((uint32_t)c4 & 63u) * 2u) ^ ((uint32_t)(mm & 7) << 4));
    char* base = (char*)act + (size_t)ht * 65536 + (size_t)(c4 >> 6) * 16384 + woff;
    uint2 v;
    v.x = pack_hi2(s0, s1); v.y = pack_hi2(s2, s3); *(uint2*)(base)         = v;
    v.x = pack_lo2(s0, s1); v.y = pack_lo2(s2, s3); *(uint2*)(base + 8192)  = v;
    v.x = pack_hi2(d0, d1); v.y = pack_hi2(d2, d3); *(uint2*)(base + 32768) = v;
    v.x = pack_lo2(d0, d1); v.y = pack_lo2(d2, d3); *(uint2*)(base + 40960) = v;
}

// ---------------------------------------------------------------------------
// Fused 4-layer kernel: two independent 8-warp row-groups pipeline the
// epilogue of one group against the MMAs of the other.
// ---------------------------------------------------------------------------
__global__ void __launch_bounds__(THREADS, 1) fused_kernel(
    const unsigned short* __restrict__ actIn,
    const char* __restrict__ wimgB,
    const float* __restrict__ cbp, const float* __restrict__ brp,
    const float* __restrict__ bip, const float* __restrict__ lowp,
    const float* __restrict__ lobp, float* __restrict__ gout)
{
    extern __shared__ char dsm_raw[];
    __shared__ __align__(8) uint64_t s_mbar[3];
    __shared__ int s_cnt;
    uint32_t raw = smem_u32(dsm_raw);
    uint32_t sbase = (raw + 127) & ~127u;
    char* sm = dsm_raw + (sbase - raw);

    int tid = threadIdx.x, wid = tid >> 5, lane = tid & 31;
    int g = wid >> 3;          // row-group: rows [32g, 32g+32)
    int widg = wid & 7;
    int tidg = tid & 255;
    int ng = widg & 3;         // n-group
    int ms = widg >> 2;        // m-slice (16 rows)

    uint32_t mbA  = smem_u32(&s_mbar[0]);
    uint32_t mbB0 = smem_u32(&s_mbar[1]);
    uint32_t mbB1 = smem_u32(&s_mbar[2]);

    int nloc = (NHT - blockIdx.x + GRID - 1) / GRID;

    if (tid == 0) {
        s_cnt = 0;
        MBAR_INIT(mbA, 1); MBAR_INIT(mbB0, 1); MBAR_INIT(mbB1, 1);
        MBAR_EXPECT(mbA, 65536u);
        BULK_G2S(sbase, (const char*)actIn + (size_t)blockIdx.x * 65536, 65536u, mbA);
        MBAR_EXPECT(mbB0, 65536u);
        BULK_G2S(sbase + SM_B0, wimgB, 65536u, mbB0);
        MBAR_EXPECT(mbB1, 65536u);
        BULK_G2S(sbase + SM_B1, wimgB + 65536, 65536u, mbB1);
    }
    {
        float* bf = (float*)(sm + SM_BIAS);
        bf[tid]        = __ldg(cbp + tid);
        bf[512 + tid]  = __ldg(brp + tid);
        bf[1024 + tid] = __ldg(bip + tid);
        if (tid < 128) bf[1536 + tid] = __ldg(lowp + tid);
    }
    __syncthreads();

    int grp = lane >> 3, lr = lane & 7;
    uint32_t xm = (uint32_t)(lr << 4);
    uint32_t a_c16 = (uint32_t)((grp >> 1) << 4);
    uint32_t b_c16 = (uint32_t)((grp & 1) << 4);
    uint32_t arowb = (uint32_t)(g * 32 + ms * 16 + lr + ((grp & 1) << 3)) * 128u;
    uint32_t brow[2];
    #pragma unroll
    for (int np = 0; np < 2; np++)
        brow[np] = (uint32_t)(ng * 32 + np * 16 + lr + ((grp >> 1) << 3)) * 128u;

    float* redg = (float*)(sm + SM_RED) + g * 256;
    int na = 0, nb0 = 0, nb1 = 0;

    for (int i = 0; i < nloc; i++) {
        int ht = blockIdx.x + i * GRID;
        int t = ht >> 1, hx = ht & 1;
        int b = t / TPI, tt = t - b * TPI;
        int r, x0;
        decode_ctile(tt, r, x0);
        int x0h = x0 + hx * 64;
        bool row0 = (r == 0);
        bool haveNext = (i + 1 < nloc);

        MBAR_WAIT(mbA, na & 1); na++;

        #pragma unroll 1
        for (int l = 0; l < 4; l++) {
            float accP[4][4], accQ[4][4];
            #pragma unroll
            for (int nt = 0; nt < 4; nt++)
                #pragma unroll
                for (int z = 0; z < 4; z++) { accP[nt][z] = 0.0f; accQ[nt][z] = 0.0f; }

            MBAR_WAIT(mbB0, nb0 & 1); nb0++;
            mma_bank(accP, sbase, sbase + SM_B0, arowb, brow, a_c16, b_c16, xm);
            MBAR_WAIT(mbB1, nb1 & 1); nb1++;
            mma_bank(accQ, sbase + 32768u, sbase + SM_B1, arowb, brow, a_c16, b_c16, xm);

            GBAR(g);   // this group's A/B reads for layer l complete
            if (tidg == 0) {
                int o = atomicAdd(&s_cnt, 1);
                if (o == 1) {      // last group to arrive issues next loads
                    s_cnt = 0;
                    if (l < 3) {
                        MBAR_EXPECT(mbB0, 65536u);
                        BULK_G2S(sbase + SM_B0, wimgB + (size_t)(l + 1) * 131072, 65536u, mbB0);
                        MBAR_EXPECT(mbB1, 65536u);
                        BULK_G2S(sbase + SM_B1, wimgB + (size_t)(l + 1) * 131072 + 65536, 65536u, mbB1);
                    } else if (haveNext) {
                        MBAR_EXPECT(mbA, 65536u);
                        BULK_G2S(sbase, (const char*)actIn + (size_t)(ht + GRID) * 65536, 65536u, mbA);
                        MBAR_EXPECT(mbB0, 65536u);
                        BULK_G2S(sbase + SM_B0, wimgB, 65536u, mbB0);
                        MBAR_EXPECT(mbB1, 65536u);
                        BULK_G2S(sbase + SM_B1, wimgB + 65536, 65536u, mbB1);
                    }
                }
            }

            const float* cbS = (const float*)(sm + SM_BIAS) + l * 128;
            const float* brS = (const float*)(sm + SM_BIAS) + 512 + l * 128;
            const float* biS = (const float*)(sm + SM_BIAS) + 1024 + l * 128;

            if (l < 3) {
                // in-place epilogue: write s'/d' into this group's rows
                #pragma unroll
                for (int rh = 0; rh < 2; rh++) {
                    int p = g * 32 + ms * 16 + (lane >> 2) + rh * 8;
                    int xc = x0h + p;
                    int xf = (256 - xc) & 255;
                    float sxp = row0 ? __ldg(&g_sx[xc]) : 0.0f;
                    float sxf = row0 ? __ldg(&g_sx[xf]) : 0.0f;
                    uint32_t rowoff = (uint32_t)p * 128u;
                    uint32_t swz = (uint32_t)(p & 7) << 4;
                    #pragma unroll
                    for (int nt = 0; nt < 4; nt++) {
                        int n = ng * 32 + nt * 8 + (lane & 3) * 2;
                        float P0 = accP[nt][rh * 2], P1 = accP[nt][rh * 2 + 1];
                        float Q0 = accQ[nt][rh * 2], Q1 = accQ[nt][rh * 2 + 1];
                        float c0 = cbS[n], c1 = cbS[n + 1];
                        float up0 = P0 + Q0 + c0, up1 = P1 + Q1 + c1;
                        float uf0 = P0 - Q0 + c0, uf1 = P1 - Q1 + c1;
                        if (row0) {
                            float b0 = biS[n], b1 = biS[n + 1];
                            up0 += b0 * sxp; up1 += b1 * sxp;
                            uf0 += b0 * sxf; uf1 += b1 * sxf;
                            if (xc == 0) {
                                up0 += brS[n]; up1 += brS[n + 1];
                                uf0 += brS[n]; uf1 += brS[n + 1];
                            }
                        }
                        float gp0 = gelu_exact(up0), gp1 = gelu_exact(up1);
                        float gf0 = gelu_exact(uf0), gf1 = gelu_exact(uf1);
                        float s0 = gp0 + gf0, s1 = gp1 + gf1;
                        float d0 = gp0 - gf0, d1 = gp1 - gf1;
                        uint32_t off = (uint32_t)(n >> 6) * 16384u + rowoff
                                     + ((((uint32_t)n & 63u) * 2u) ^ swz);
                        *(uint32_t*)(sm + off)          = pack_hi2(s0, s1);
                        *(uint32_t*)(sm + off + 8192u)  = pack_lo2(s0, s1);
                        *(uint32_t*)(sm + off + 32768u) = pack_hi2(d0, d1);
                        *(uint32_t*)(sm + off + 40960u) = pack_lo2(d0, d1);
                    }
                }
                GBAR(g);   // group's writes visible before its next-layer MMA
            } else {
                // final fused output
                const float* lowS = (const float*)(sm + SM_BIAS) + 1536;
                #pragma unroll
                for (int rh = 0; rh < 2; rh++) {
                    int pl = ms * 16 + (lane >> 2) + rh * 8;   // 0..31 in group
                    int p = g * 32 + pl;
                    int xc = x0h + p;
                    int xf = (256 - xc) & 255;
                    float sxp = row0 ? __ldg(&g_sx[xc]) : 0.0f;
                    float sxf = row0 ? __ldg(&g_sx[xf]) : 0.0f;
                    float pp = 0.0f, pf = 0.0f;
                    #pragma unroll
                    for (int nt = 0; nt < 4; nt++) {
                        int n = ng * 32 + nt * 8 + (lane & 3) * 2;
                        float P0 = accP[nt][rh * 2], P1 = accP[nt][rh * 2 + 1];
                        float Q0 = accQ[nt][rh * 2], Q1 = accQ[nt][rh * 2 + 1];
                        float c0 = cbS[n], c1 = cbS[n + 1];
                        float up0 = P0 + Q0 + c0, up1 = P1 + Q1 + c1;
                        float uf0 = P0 - Q0 + c0, uf1 = P1 - Q1 + c1;
                        if (row0) {
                            float b0 = biS[n], b1 = biS[n + 1];
                            up0 += b0 * sxp; up1 += b1 * sxp;
                            uf0 += b0 * sxf; uf1 += b1 * sxf;
                            if (xc == 0) {
                                up0 += brS[n]; up1 += brS[n + 1];
                                uf0 += brS[n]; uf1 += brS[n + 1];
                            }
                        }
                        pp += gelu_exact(up0) * lowS[n] + gelu_exact(up1) * lowS[n + 1];
                        pf += gelu_exact(uf0) * lowS[n] + gelu_exact(uf1) * lowS[n + 1];
                    }
                    pp += __shfl_xor_sync(0xffffffffu, pp, 1);
                    pp += __shfl_xor_sync(0xffffffffu, pp, 2);
                    pf += __shfl_xor_sync(0xffffffffu, pf, 1);
                    pf += __shfl_xor_sync(0xffffffffu, pf, 2);
                    if ((lane & 3) == 0) {
                        redg[ng * 32 + pl]       = pp;
                        redg[128 + ng * 32 + pl] = pf;
                    }
                }
                GBAR(g);
                if (tidg < 32) {
                    float lob = __ldg(lobp);
                    int pl = tidg;
                    float sp = redg[pl] + redg[32 + pl] + redg[64 + pl] + redg[96 + pl];
                    float sf = redg[128 + pl] + redg[160 + pl] + redg[192 + pl] + redg[224 + pl];
                    int p = g * 32 + pl;
                    int xc = x0h + p, xf = (256 - xc) & 255, rf = (256 - r) & 255;
                    gout[(size_t)b * 65536 + r * 256 + xc]  = gelu_exact(sp + lob);
                    gout[(size_t)b * 65536 + rf * 256 + xf] = gelu_exact(sf + lob);
                }
                GBAR(g);
            }
        }
    }
}

// ---------------------------------------------------------------------------
extern "C" void kernel_launch(void* const* d_in, const int* in_sizes, int n_in,
                              void* d_out, int out_size)
{
    const float* x   = (const float*)d_in[0];
    const float* liw = (const float*)d_in[1];
    const float* lib = (const float*)d_in[2];
    const float* wr  = (const float*)d_in[3];
    const float* wi  = (const float*)d_in[4];
    const float* br  = (const float*)d_in[5];
    const float* bi  = (const float*)d_in[6];
    const float* cw  = (const float*)d_in[7];
    const float* cb  = (const float*)d_in[8];
    const float* low = (const float*)d_in[9];
    const float* lob = (const float*)d_in[10];
    float* out = (float*)d_out;

    unsigned short *a0, *wimg;
    float* sx;
    cudaGetSymbolAddress((void**)&a0, g_act0);
    cudaGetSymbolAddress((void**)&wimg, g_wimg);
    cudaGetSymbolAddress((void**)&sx, g_sx);

    cudaFuncSetAttribute(fused_kernel, cudaFuncAttributeMaxDynamicSharedMemorySize, SM_DYN);

    prep_w_kernel<<<512, 256>>>(wr, wi, cw, wimg);
    prep_sx_kernel<<<1, 256>>>(sx);
    in_kernel<<<NTILE_TOT * 128 * 32 / 256, 256>>>(x, liw, lib, a0);

    fused_kernel<<<GRID, THREADS, SM_DYN>>>(
        a0, (const char*)wimg, cb, br, bi, low, lob, out);
}